// round 1
// baseline (speedup 1.0000x reference)
#include <cuda_runtime.h>

#define BATCH 2
#define SEQ   2048
#define DIM   1024
#define NH    16
#define HD    64
#define MROWS (BATCH*SEQ)   // 4096
#define QKVN  (3*DIM)       // 3072

// Scratch (allocation-free rule: __device__ globals)
__device__ float g_Q[(size_t)BATCH*NH*SEQ*HD];
__device__ float g_K[(size_t)BATCH*NH*SEQ*HD];
__device__ float g_V[(size_t)BATCH*NH*SEQ*HD];
__device__ float g_att[(size_t)MROWS*DIM];

// ---------------------------------------------------------------------------
// GEMM 1: QKV projection. C[4096,3072] = X[4096,1024] @ Wqkv[1024,3072] + bqkv
// Epilogue scatters into g_Q/g_K/g_V laid out [B][H][S][hd].
// 128x128 block tile, BK=8, 256 threads, 8x8 per-thread micro-tile (split 4+4).
// ---------------------------------------------------------------------------
__global__ __launch_bounds__(256) void gemm_qkv_kernel(
    const float* __restrict__ X, const float* __restrict__ W,
    const float* __restrict__ bias)
{
    __shared__ float As[8][128];
    __shared__ float Bs[8][128];
    const int tid  = threadIdx.x;
    const int tx   = tid & 15;
    const int ty   = tid >> 4;
    const int row0 = blockIdx.y * 128;
    const int col0 = blockIdx.x * 128;
    const int K = DIM, N = QKVN;

    float acc[8][8];
#pragma unroll
    for (int i = 0; i < 8; i++)
#pragma unroll
        for (int j = 0; j < 8; j++) acc[i][j] = 0.f;

    const int ar = tid >> 1, ac = (tid & 1) * 4;
    const int br = tid >> 5, bc = (tid & 31) * 4;

    for (int k0 = 0; k0 < K; k0 += 8) {
        float4 a = *(const float4*)(X + (size_t)(row0 + ar) * K + k0 + ac);
        As[ac + 0][ar] = a.x;
        As[ac + 1][ar] = a.y;
        As[ac + 2][ar] = a.z;
        As[ac + 3][ar] = a.w;
        *(float4*)&Bs[br][bc] = *(const float4*)(W + (size_t)(k0 + br) * N + col0 + bc);
        __syncthreads();
#pragma unroll
        for (int kk = 0; kk < 8; kk++) {
            float a0[8], b0[8];
            *(float4*)&a0[0] = *(float4*)&As[kk][ty * 4];
            *(float4*)&a0[4] = *(float4*)&As[kk][64 + ty * 4];
            *(float4*)&b0[0] = *(float4*)&Bs[kk][tx * 4];
            *(float4*)&b0[4] = *(float4*)&Bs[kk][64 + tx * 4];
#pragma unroll
            for (int i = 0; i < 8; i++)
#pragma unroll
                for (int j = 0; j < 8; j++)
                    acc[i][j] += a0[i] * b0[j];
        }
        __syncthreads();
    }

    // Epilogue: scatter float4s into Q/K/V [B][H][S][hd]
#pragma unroll
    for (int jg = 0; jg < 2; jg++) {
        const int c0  = col0 + jg * 64 + tx * 4;
        const int sel = c0 >> 10;          // which of q/k/v
        const int w   = c0 & 1023;
        const int h   = w >> 6;
        const int d0  = w & 63;
        float* dst = (sel == 0) ? g_Q : (sel == 1) ? g_K : g_V;
        const float4 bb = *(const float4*)(bias + c0);
#pragma unroll
        for (int ig = 0; ig < 2; ig++) {
#pragma unroll
            for (int ii = 0; ii < 4; ii++) {
                const int i = ig * 4 + ii;
                const int r = row0 + ig * 64 + ty * 4 + ii;
                const int b = r >> 11;      // /SEQ
                const int s = r & 2047;
                float4 v;
                v.x = acc[i][jg * 4 + 0] + bb.x;
                v.y = acc[i][jg * 4 + 1] + bb.y;
                v.z = acc[i][jg * 4 + 2] + bb.z;
                v.w = acc[i][jg * 4 + 3] + bb.w;
                *(float4*)(dst + (((size_t)b * NH + h) * SEQ + s) * HD + d0) = v;
            }
        }
    }
}

// ---------------------------------------------------------------------------
// GEMM 2: output projection. out[4096,1024] = g_att[4096,1024] @ Wout + bout
// ---------------------------------------------------------------------------
__global__ __launch_bounds__(256) void gemm_out_kernel(
    const float* __restrict__ W, const float* __restrict__ bias,
    float* __restrict__ out)
{
    __shared__ float As[8][128];
    __shared__ float Bs[8][128];
    const int tid  = threadIdx.x;
    const int tx   = tid & 15;
    const int ty   = tid >> 4;
    const int row0 = blockIdx.y * 128;
    const int col0 = blockIdx.x * 128;
    const int K = DIM, N = DIM;

    float acc[8][8];
#pragma unroll
    for (int i = 0; i < 8; i++)
#pragma unroll
        for (int j = 0; j < 8; j++) acc[i][j] = 0.f;

    const int ar = tid >> 1, ac = (tid & 1) * 4;
    const int br = tid >> 5, bc = (tid & 31) * 4;

    for (int k0 = 0; k0 < K; k0 += 8) {
        float4 a = *(const float4*)(g_att + (size_t)(row0 + ar) * K + k0 + ac);
        As[ac + 0][ar] = a.x;
        As[ac + 1][ar] = a.y;
        As[ac + 2][ar] = a.z;
        As[ac + 3][ar] = a.w;
        *(float4*)&Bs[br][bc] = *(const float4*)(W + (size_t)(k0 + br) * N + col0 + bc);
        __syncthreads();
#pragma unroll
        for (int kk = 0; kk < 8; kk++) {
            float a0[8], b0[8];
            *(float4*)&a0[0] = *(float4*)&As[kk][ty * 4];
            *(float4*)&a0[4] = *(float4*)&As[kk][64 + ty * 4];
            *(float4*)&b0[0] = *(float4*)&Bs[kk][tx * 4];
            *(float4*)&b0[4] = *(float4*)&Bs[kk][64 + tx * 4];
#pragma unroll
            for (int i = 0; i < 8; i++)
#pragma unroll
                for (int j = 0; j < 8; j++)
                    acc[i][j] += a0[i] * b0[j];
        }
        __syncthreads();
    }

#pragma unroll
    for (int jg = 0; jg < 2; jg++) {
        const int c0 = col0 + jg * 64 + tx * 4;
        const float4 bb = *(const float4*)(bias + c0);
#pragma unroll
        for (int ig = 0; ig < 2; ig++) {
#pragma unroll
            for (int ii = 0; ii < 4; ii++) {
                const int i = ig * 4 + ii;
                const int r = row0 + ig * 64 + ty * 4 + ii;
                float4 v;
                v.x = acc[i][jg * 4 + 0] + bb.x;
                v.y = acc[i][jg * 4 + 1] + bb.y;
                v.z = acc[i][jg * 4 + 2] + bb.z;
                v.w = acc[i][jg * 4 + 3] + bb.w;
                *(float4*)(out + (size_t)r * DIM + c0) = v;
            }
        }
    }
}

// ---------------------------------------------------------------------------
// Flash attention (fp32, online softmax). One block = 64 queries x one (b,h).
// Qst/Kst stored d-major with XOR swizzle (kills the 16-way transpose-STS
// conflicts that a padded layout cannot avoid since stride must stay %4==0).
// ---------------------------------------------------------------------------
__device__ __forceinline__ int swz(int d, int q) {
    // d-major [64][64], 4-float-group XOR swizzle
    return d * 64 + ((((q >> 2) ^ ((d >> 2) & 15)) << 2) | (q & 3));
}

#define ATTN_SMEM ((2*64*64 + 2*64*68) * 4)   // 67584 bytes

__global__ __launch_bounds__(256) void attn_kernel(
    const float* __restrict__ mask, const float* __restrict__ bias)
{
    extern __shared__ float sm[];
    float* Qst = sm;                         // [64][64] swizzled (d, q)
    float* Kst = sm + 64 * 64;               // [64][64] swizzled (d, key)
    float* Vs  = sm + 2 * 64 * 64;           // [64][68]  (key, d)
    float* Ps  = sm + 2 * 64 * 64 + 64 * 68; // [64][68]  (q, key)

    const int tid = threadIdx.x;
    const int tx  = tid & 15;
    const int ty  = tid >> 4;
    const int bh  = blockIdx.y;
    const int b   = bh >> 4;
    const int h   = bh & 15;
    const int q0  = blockIdx.x * 64;

    const float* Qg = g_Q + (size_t)bh * SEQ * HD;
    const float* Kg = g_K + (size_t)bh * SEQ * HD;
    const float* Vg = g_V + (size_t)bh * SEQ * HD;
    const float* biasb = bias + (size_t)b * SEQ * SEQ;

    // Load Q tile transposed + swizzled (once)
#pragma unroll
    for (int it = 0; it < 4; it++) {
        const int e  = tid + it * 256;
        const int q  = e >> 4;
        const int dg = (e & 15) * 4;
        float4 v = *(const float4*)(Qg + (size_t)(q0 + q) * HD + dg);
        Qst[swz(dg + 0, q)] = v.x;
        Qst[swz(dg + 1, q)] = v.y;
        Qst[swz(dg + 2, q)] = v.z;
        Qst[swz(dg + 3, q)] = v.w;
    }

    float m[4], l[4], o[4][4];
#pragma unroll
    for (int i = 0; i < 4; i++) {
        m[i] = -1e30f;
        l[i] = 0.f;
#pragma unroll
        for (int j = 0; j < 4; j++) o[i][j] = 0.f;
    }

    for (int kt = 0; kt < SEQ / 64; kt++) {
        const int k0 = kt * 64;
        // Load K (transposed+swizzled) and V tiles
#pragma unroll
        for (int it = 0; it < 4; it++) {
            const int e  = tid + it * 256;
            const int r  = e >> 4;
            const int dg = (e & 15) * 4;
            float4 kv = *(const float4*)(Kg + (size_t)(k0 + r) * HD + dg);
            Kst[swz(dg + 0, r)] = kv.x;
            Kst[swz(dg + 1, r)] = kv.y;
            Kst[swz(dg + 2, r)] = kv.z;
            Kst[swz(dg + 3, r)] = kv.w;
            *(float4*)(Vs + r * 68 + dg) = *(const float4*)(Vg + (size_t)(k0 + r) * HD + dg);
        }
        __syncthreads();

        // scores[q=ty*4+i][key=tx*4+j] = Q . K over d
        float sc[4][4];
#pragma unroll
        for (int i = 0; i < 4; i++)
#pragma unroll
            for (int j = 0; j < 4; j++) sc[i][j] = 0.f;

#pragma unroll 16
        for (int d = 0; d < 64; d++) {
            const int sa = (d >> 2) & 15;
            float a4[4], b4[4];
            *(float4*)a4 = *(float4*)(Qst + d * 64 + ((ty ^ sa) << 2));
            *(float4*)b4 = *(float4*)(Kst + d * 64 + ((tx ^ sa) << 2));
#pragma unroll
            for (int i = 0; i < 4; i++)
#pragma unroll
                for (int j = 0; j < 4; j++)
                    sc[i][j] += a4[i] * b4[j];
        }

        // scale + mask + bias
#pragma unroll
        for (int i = 0; i < 4; i++) {
            const size_t roff = (size_t)(q0 + ty * 4 + i) * SEQ + k0 + tx * 4;
            const float4 mm = *(const float4*)(mask + roff);
            const float4 bbv = *(const float4*)(biasb + roff);
            sc[i][0] = sc[i][0] * 0.125f + mm.x + bbv.x;
            sc[i][1] = sc[i][1] * 0.125f + mm.y + bbv.y;
            sc[i][2] = sc[i][2] * 0.125f + mm.z + bbv.z;
            sc[i][3] = sc[i][3] * 0.125f + mm.w + bbv.w;
        }

        // row max across the 16 tx lanes
        float rm[4];
#pragma unroll
        for (int i = 0; i < 4; i++) {
            rm[i] = fmaxf(fmaxf(sc[i][0], sc[i][1]), fmaxf(sc[i][2], sc[i][3]));
#pragma unroll
            for (int ofs = 8; ofs >= 1; ofs >>= 1)
                rm[i] = fmaxf(rm[i], __shfl_xor_sync(0xffffffffu, rm[i], ofs));
        }

        // online softmax update
        float rs[4];
#pragma unroll
        for (int i = 0; i < 4; i++) {
            const float mn = fmaxf(m[i], rm[i]);
            const float c  = __expf(m[i] - mn);
            m[i] = mn;
            l[i] *= c;
#pragma unroll
            for (int j = 0; j < 4; j++) o[i][j] *= c;
            float s = 0.f;
#pragma unroll
            for (int j = 0; j < 4; j++) {
                sc[i][j] = __expf(sc[i][j] - mn);
                s += sc[i][j];
            }
#pragma unroll
            for (int ofs = 8; ofs >= 1; ofs >>= 1)
                s += __shfl_xor_sync(0xffffffffu, s, ofs);
            rs[i] = s;
        }
#pragma unroll
        for (int i = 0; i < 4; i++) l[i] += rs[i];

        // write P tile (float4 rows, natural layout)
#pragma unroll
        for (int i = 0; i < 4; i++) {
            float4 p4;
            p4.x = sc[i][0]; p4.y = sc[i][1]; p4.z = sc[i][2]; p4.w = sc[i][3];
            *(float4*)(Ps + (ty * 4 + i) * 68 + tx * 4) = p4;
        }
        __syncthreads();

        // O += P @ V   (o cols = hd = tx*4+j)
#pragma unroll 16
        for (int k = 0; k < 64; k++) {
            const float a0 = Ps[(ty * 4 + 0) * 68 + k];
            const float a1 = Ps[(ty * 4 + 1) * 68 + k];
            const float a2 = Ps[(ty * 4 + 2) * 68 + k];
            const float a3 = Ps[(ty * 4 + 3) * 68 + k];
            float b4[4];
            *(float4*)b4 = *(float4*)(Vs + k * 68 + tx * 4);
#pragma unroll
            for (int j = 0; j < 4; j++) {
                o[0][j] += a0 * b4[j];
                o[1][j] += a1 * b4[j];
                o[2][j] += a2 * b4[j];
                o[3][j] += a3 * b4[j];
            }
        }
        __syncthreads();
    }

    // normalize and write to g_att laid out [B][S][H][hd] (= [4096,1024])
#pragma unroll
    for (int i = 0; i < 4; i++) {
        const float inv = 1.f / l[i];
        const int q = q0 + ty * 4 + i;
        float4 v;
        v.x = o[i][0] * inv;
        v.y = o[i][1] * inv;
        v.z = o[i][2] * inv;
        v.w = o[i][3] * inv;
        *(float4*)(g_att + ((size_t)(b * SEQ + q) * DIM) + h * HD + tx * 4) = v;
    }
}

// ---------------------------------------------------------------------------
extern "C" void kernel_launch(void* const* d_in, const int* in_sizes, int n_in,
                              void* d_out, int out_size)
{
    const float* x     = (const float*)d_in[0];
    const float* mask  = (const float*)d_in[1];
    const float* bias  = (const float*)d_in[2];
    const float* Wqkv  = (const float*)d_in[3];
    const float* bqkv  = (const float*)d_in[4];
    const float* Wout  = (const float*)d_in[5];
    const float* bout  = (const float*)d_in[6];
    float* out = (float*)d_out;

    cudaFuncSetAttribute(attn_kernel,
                         cudaFuncAttributeMaxDynamicSharedMemorySize, ATTN_SMEM);

    gemm_qkv_kernel<<<dim3(QKVN / 128, MROWS / 128), 256>>>(x, Wqkv, bqkv);
    attn_kernel<<<dim3(SEQ / 64, BATCH * NH), 256, ATTN_SMEM>>>(mask, bias);
    gemm_out_kernel<<<dim3(DIM / 128, MROWS / 128), 256>>>(Wout, bout, out);
}

// round 3
// speedup vs baseline: 1.4572x; 1.4572x over previous
#include <cuda_runtime.h>
#include <cuda_bf16.h>

#define BATCH 2
#define SEQ   2048
#define DIM   1024
#define NH    16
#define HD    64
#define MROWS (BATCH*SEQ)   // 4096
#define QKVN  (3*DIM)       // 3072

// ---------------- scratch (__device__ globals; no runtime allocs) ----------
__device__ float g_Q[(size_t)BATCH*NH*SEQ*HD];
__device__ float g_K[(size_t)BATCH*NH*SEQ*HD];
__device__ float g_V[(size_t)BATCH*NH*SEQ*HD];
__device__ __nv_bfloat16 g_Xhi[(size_t)MROWS*DIM];
__device__ __nv_bfloat16 g_Xlo[(size_t)MROWS*DIM];
__device__ __nv_bfloat16 g_W1hi[(size_t)QKVN*DIM];   // Wqkv^T [3072][1024]
__device__ __nv_bfloat16 g_W1lo[(size_t)QKVN*DIM];
__device__ __nv_bfloat16 g_W2hi[(size_t)DIM*DIM];    // Wout^T [1024][1024]
__device__ __nv_bfloat16 g_W2lo[(size_t)DIM*DIM];
__device__ __nv_bfloat16 g_AOhi[(size_t)MROWS*DIM];  // attention out hi/lo
__device__ __nv_bfloat16 g_AOlo[(size_t)MROWS*DIM];

// ---------------- helpers ---------------------------------------------------
__device__ __forceinline__ unsigned smem_u32(const void* p) {
    unsigned a;
    asm("{ .reg .u64 t; cvta.to.shared.u64 t, %1; cvt.u32.u64 %0, t; }"
        : "=r"(a) : "l"(p));
    return a;
}
__device__ __forceinline__ void ldsm4(unsigned& r0, unsigned& r1,
                                      unsigned& r2, unsigned& r3, unsigned a) {
    asm volatile("ldmatrix.sync.aligned.m8n8.x4.shared.b16 {%0,%1,%2,%3}, [%4];"
                 : "=r"(r0), "=r"(r1), "=r"(r2), "=r"(r3) : "r"(a));
}
__device__ __forceinline__ void mma_bf16(float* c, const unsigned* a,
                                         unsigned b0, unsigned b1) {
    asm volatile(
        "mma.sync.aligned.m16n8k16.row.col.f32.bf16.bf16.f32 "
        "{%0,%1,%2,%3}, {%4,%5,%6,%7}, {%8,%9}, {%0,%1,%2,%3};"
        : "+f"(c[0]), "+f"(c[1]), "+f"(c[2]), "+f"(c[3])
        : "r"(a[0]), "r"(a[1]), "r"(a[2]), "r"(a[3]), "r"(b0), "r"(b1));
}
__device__ __forceinline__ void cp16(unsigned dst, const void* src) {
    asm volatile("cp.async.cg.shared.global [%0], [%1], 16;"
                 :: "r"(dst), "l"(src) : "memory");
}
__device__ __forceinline__ void cp_commit() {
    asm volatile("cp.async.commit_group;" ::: "memory");
}

#define GEMM_SMEM (2*65536)   // 2 stages x (Ahi|Alo|Bhi|Blo) 16KB tiles

// ---------------------------------------------------------------------------
// conversions
// ---------------------------------------------------------------------------
__global__ __launch_bounds__(256) void conv_split_kernel(
    const float* __restrict__ src, __nv_bfloat16* __restrict__ hi,
    __nv_bfloat16* __restrict__ lo, int n4)
{
    int i = blockIdx.x * 256 + threadIdx.x;
    if (i >= n4) return;
    float4 v = *((const float4*)src + i);
    __nv_bfloat162 h01, h23, l01, l23;
    h01.x = __float2bfloat16(v.x); h01.y = __float2bfloat16(v.y);
    h23.x = __float2bfloat16(v.z); h23.y = __float2bfloat16(v.w);
    l01.x = __float2bfloat16(v.x - __bfloat162float(h01.x));
    l01.y = __float2bfloat16(v.y - __bfloat162float(h01.y));
    l23.x = __float2bfloat16(v.z - __bfloat162float(h23.x));
    l23.y = __float2bfloat16(v.w - __bfloat162float(h23.y));
    ((__nv_bfloat162*)hi)[i*2+0] = h01;
    ((__nv_bfloat162*)hi)[i*2+1] = h23;
    ((__nv_bfloat162*)lo)[i*2+0] = l01;
    ((__nv_bfloat162*)lo)[i*2+1] = l23;
}

// transpose + split: W[K][N] -> T{hi,lo}[N][K]
__global__ void conv_transpose_kernel(
    const float* __restrict__ W, __nv_bfloat16* __restrict__ Thi,
    __nv_bfloat16* __restrict__ Tlo, int K, int N)
{
    __shared__ float t[32][33];
    const int k0 = blockIdx.x * 32, n0 = blockIdx.y * 32;
    const int tx = threadIdx.x, ty = threadIdx.y;   // (32,8)
    for (int i = ty; i < 32; i += 8)
        t[i][tx] = W[(size_t)(k0 + i) * N + n0 + tx];
    __syncthreads();
    for (int i = ty; i < 32; i += 8) {
        float v = t[tx][i];
        __nv_bfloat16 h = __float2bfloat16(v);
        Thi[(size_t)(n0 + i) * K + k0 + tx] = h;
        Tlo[(size_t)(n0 + i) * K + k0 + tx] =
            __float2bfloat16(v - __bfloat162float(h));
    }
}

// ---------------------------------------------------------------------------
// HMMA split-bf16 GEMM: C[m][n] = sum_k A[m][k]*B[n][k] + bias[n]
// A = Ahi+Alo [M][1024], B = Bhi+Blo [NB][1024] (pre-transposed weights).
// 128x128 CTA tile, 8 warps (4 x 2), warp tile 32x64, BK=64,
// cp.async 2-stage pipeline, ldmatrix + mma.sync m16n8k16 bf16.
// mode 0: out[m][1024] += bias. mode 1: scatter into g_Q/g_K/g_V.
// ---------------------------------------------------------------------------
__global__ __launch_bounds__(256) void mma_gemm_kernel(
    const __nv_bfloat16* __restrict__ Ahi, const __nv_bfloat16* __restrict__ Alo,
    const __nv_bfloat16* __restrict__ Bhi, const __nv_bfloat16* __restrict__ Blo,
    const float* __restrict__ bias, float* __restrict__ out, int mode)
{
    extern __shared__ char smraw[];
    const unsigned sbase = smem_u32(smraw);
    const int tid  = threadIdx.x;
    const int wid  = tid >> 5;
    const int lane = tid & 31;
    const int warp_m = wid & 3;           // 0..3  -> 32 rows each
    const int warp_n = wid >> 2;          // 0..1  -> 64 cols each
    const int row_a = blockIdx.y * 128;
    const int col0  = blockIdx.x * 128;

    float acc[2][8][4];
#pragma unroll
    for (int i = 0; i < 2; i++)
#pragma unroll
        for (int j = 0; j < 8; j++)
#pragma unroll
            for (int c = 0; c < 4; c++) acc[i][j][c] = 0.f;

    // --- async tile loader: tiles Ahi|Alo|Bhi|Blo, each [128 rows][64 bf16] ---
    const int lrow  = tid >> 1;              // load thread -> handles... (see below)
    (void)lrow;
    auto issue = [&](int t) {
        const int k0 = t * 64;
        const unsigned stage = (unsigned)((t & 1) * 65536);
#pragma unroll
        for (int p = 0; p < 4; p++) {
            const __nv_bfloat16* src = (p == 0) ? Ahi : (p == 1) ? Alo
                                     : (p == 2) ? Bhi : Blo;
            const int rb = (p < 2) ? row_a : col0;
            const unsigned pb = stage + (unsigned)p * 16384u;
#pragma unroll
            for (int i = 0; i < 4; i++) {
                const int e = tid + i * 256;
                const int r = e >> 3, c4 = e & 7;      // r:0..127, c4:0..7 (16B units)
                unsigned off = (unsigned)(r * 128 + c4 * 16);
                off ^= (off >> 3) & 0x70;
                cp16(sbase + pb + off,
                     src + (size_t)(rb + r) * DIM + k0 + c4 * 8);
            }
        }
        cp_commit();
    };

    issue(0);
    issue(1);

    // lane-fixed ldmatrix base addresses (row part + xor mask), per fragment
    const int amat = lane >> 3;
    const int arow = warp_m * 32 + (lane & 7) + ((amat & 1) << 3);   // + mf*16
    const unsigned acolx = (unsigned)((amat >> 1) << 4);
    const int brow = warp_n * 64 + (lane & 7) + ((amat >> 1) << 3);  // + npair*16
    const unsigned bcolx = (unsigned)((amat & 1) << 4);

    for (int t = 0; t < 16; t++) {
        if (t < 15)
            asm volatile("cp.async.wait_group 1;" ::: "memory");
        else
            asm volatile("cp.async.wait_group 0;" ::: "memory");
        __syncthreads();

        const unsigned stage = (unsigned)((t & 1) * 65536);
#pragma unroll
        for (int ks = 0; ks < 4; ks++) {
            const unsigned kb = (unsigned)(ks * 32);
            unsigned ah[2][4], al[2][4], bh[4][4], bl[4][4];
#pragma unroll
            for (int mf = 0; mf < 2; mf++) {
                const int r = arow + mf * 16;
                const unsigned ro = (unsigned)(r * 128) + ((kb + acolx) ^ (((unsigned)(r & 7)) << 4));
                ldsm4(ah[mf][0], ah[mf][1], ah[mf][2], ah[mf][3], sbase + stage + ro);
                ldsm4(al[mf][0], al[mf][1], al[mf][2], al[mf][3], sbase + stage + 16384 + ro);
            }
#pragma unroll
            for (int np = 0; np < 4; np++) {
                const int r = brow + np * 16;
                const unsigned ro = (unsigned)(r * 128) + ((kb + bcolx) ^ (((unsigned)(r & 7)) << 4));
                ldsm4(bh[np][0], bh[np][1], bh[np][2], bh[np][3], sbase + stage + 32768 + ro);
                ldsm4(bl[np][0], bl[np][1], bl[np][2], bl[np][3], sbase + stage + 49152 + ro);
            }
#pragma unroll
            for (int mf = 0; mf < 2; mf++) {
#pragma unroll
                for (int nn = 0; nn < 8; nn++) {
                    const int np = nn >> 1, hf = (nn & 1) * 2;
                    mma_bf16(acc[mf][nn], ah[mf], bh[np][hf], bh[np][hf + 1]);
                    mma_bf16(acc[mf][nn], ah[mf], bl[np][hf], bl[np][hf + 1]);
                    mma_bf16(acc[mf][nn], al[mf], bh[np][hf], bh[np][hf + 1]);
                }
            }
        }
        if (t + 2 < 16) {
            __syncthreads();
            issue(t + 2);
        }
    }

    // --- epilogue: direct frag -> global (float2 per reg pair) ---
#pragma unroll
    for (int mf = 0; mf < 2; mf++) {
#pragma unroll
        for (int nn = 0; nn < 8; nn++) {
            const int gc = col0 + warp_n * 64 + nn * 8 + (lane & 3) * 2;
            const int r0 = row_a + warp_m * 32 + mf * 16 + (lane >> 2);
            const float bx = bias[gc], by = bias[gc + 1];
            float2 v0, v1;
            v0.x = acc[mf][nn][0] + bx; v0.y = acc[mf][nn][1] + by;
            v1.x = acc[mf][nn][2] + bx; v1.y = acc[mf][nn][3] + by;
            if (mode == 0) {
                *(float2*)(out + (size_t)r0 * DIM + gc)       = v0;
                *(float2*)(out + (size_t)(r0 + 8) * DIM + gc) = v1;
            } else {
                const int sel = gc >> 10;
                const int w   = gc & 1023;
                const int h   = w >> 6;
                const int d0  = w & 63;
                float* dst = (sel == 0) ? g_Q : (sel == 1) ? g_K : g_V;
                const int b0 = r0 >> 11, s0 = r0 & 2047;
                const int r1 = r0 + 8;
                const int b1 = r1 >> 11, s1 = r1 & 2047;
                *(float2*)(dst + (((size_t)b0 * NH + h) * SEQ + s0) * HD + d0) = v0;
                *(float2*)(dst + (((size_t)b1 * NH + h) * SEQ + s1) * HD + d0) = v1;
            }
        }
    }
}

// ---------------------------------------------------------------------------
// Flash attention (fp32, online softmax). Epilogue emits bf16 hi/lo.
// ---------------------------------------------------------------------------
__device__ __forceinline__ int swz(int d, int q) {
    return d * 64 + ((((q >> 2) ^ ((d >> 2) & 15)) << 2) | (q & 3));
}

#define ATTN_SMEM ((2*64*64 + 2*64*68) * 4)

__global__ __launch_bounds__(256) void attn_kernel(
    const float* __restrict__ mask, const float* __restrict__ bias)
{
    extern __shared__ float sm[];
    float* Qst = sm;
    float* Kst = sm + 64 * 64;
    float* Vs  = sm + 2 * 64 * 64;
    float* Ps  = sm + 2 * 64 * 64 + 64 * 68;

    const int tid = threadIdx.x;
    const int tx  = tid & 15;
    const int ty  = tid >> 4;
    const int bh  = blockIdx.y;
    const int b   = bh >> 4;
    const int h   = bh & 15;
    const int q0  = blockIdx.x * 64;

    const float* Qg = g_Q + (size_t)bh * SEQ * HD;
    const float* Kg = g_K + (size_t)bh * SEQ * HD;
    const float* Vg = g_V + (size_t)bh * SEQ * HD;
    const float* biasb = bias + (size_t)b * SEQ * SEQ;

#pragma unroll
    for (int it = 0; it < 4; it++) {
        const int e  = tid + it * 256;
        const int q  = e >> 4;
        const int dg = (e & 15) * 4;
        float4 v = *(const float4*)(Qg + (size_t)(q0 + q) * HD + dg);
        Qst[swz(dg + 0, q)] = v.x;
        Qst[swz(dg + 1, q)] = v.y;
        Qst[swz(dg + 2, q)] = v.z;
        Qst[swz(dg + 3, q)] = v.w;
    }

    float m[4], l[4], o[4][4];
#pragma unroll
    for (int i = 0; i < 4; i++) {
        m[i] = -1e30f; l[i] = 0.f;
#pragma unroll
        for (int j = 0; j < 4; j++) o[i][j] = 0.f;
    }

    for (int kt = 0; kt < SEQ / 64; kt++) {
        const int k0 = kt * 64;
#pragma unroll
        for (int it = 0; it < 4; it++) {
            const int e  = tid + it * 256;
            const int r  = e >> 4;
            const int dg = (e & 15) * 4;
            float4 kv = *(const float4*)(Kg + (size_t)(k0 + r) * HD + dg);
            Kst[swz(dg + 0, r)] = kv.x;
            Kst[swz(dg + 1, r)] = kv.y;
            Kst[swz(dg + 2, r)] = kv.z;
            Kst[swz(dg + 3, r)] = kv.w;
            *(float4*)(Vs + r * 68 + dg) = *(const float4*)(Vg + (size_t)(k0 + r) * HD + dg);
        }
        __syncthreads();

        float sc[4][4];
#pragma unroll
        for (int i = 0; i < 4; i++)
#pragma unroll
            for (int j = 0; j < 4; j++) sc[i][j] = 0.f;

#pragma unroll 16
        for (int d = 0; d < 64; d++) {
            const int sa = (d >> 2) & 15;
            float a4[4], b4[4];
            *(float4*)a4 = *(float4*)(Qst + d * 64 + ((ty ^ sa) << 2));
            *(float4*)b4 = *(float4*)(Kst + d * 64 + ((tx ^ sa) << 2));
#pragma unroll
            for (int i = 0; i < 4; i++)
#pragma unroll
                for (int j = 0; j < 4; j++)
                    sc[i][j] += a4[i] * b4[j];
        }

#pragma unroll
        for (int i = 0; i < 4; i++) {
            const size_t roff = (size_t)(q0 + ty * 4 + i) * SEQ + k0 + tx * 4;
            const float4 mm  = *(const float4*)(mask + roff);
            const float4 bbv = *(const float4*)(biasb + roff);
            sc[i][0] = sc[i][0] * 0.125f + mm.x + bbv.x;
            sc[i][1] = sc[i][1] * 0.125f + mm.y + bbv.y;
            sc[i][2] = sc[i][2] * 0.125f + mm.z + bbv.z;
            sc[i][3] = sc[i][3] * 0.125f + mm.w + bbv.w;
        }

        float rm[4];
#pragma unroll
        for (int i = 0; i < 4; i++) {
            rm[i] = fmaxf(fmaxf(sc[i][0], sc[i][1]), fmaxf(sc[i][2], sc[i][3]));
#pragma unroll
            for (int ofs = 8; ofs >= 1; ofs >>= 1)
                rm[i] = fmaxf(rm[i], __shfl_xor_sync(0xffffffffu, rm[i], ofs));
        }

        float rs[4];
#pragma unroll
        for (int i = 0; i < 4; i++) {
            const float mn = fmaxf(m[i], rm[i]);
            const float c  = __expf(m[i] - mn);
            m[i] = mn;
            l[i] *= c;
#pragma unroll
            for (int j = 0; j < 4; j++) o[i][j] *= c;
            float s = 0.f;
#pragma unroll
            for (int j = 0; j < 4; j++) {
                sc[i][j] = __expf(sc[i][j] - mn);
                s += sc[i][j];
            }
#pragma unroll
            for (int ofs = 8; ofs >= 1; ofs >>= 1)
                s += __shfl_xor_sync(0xffffffffu, s, ofs);
            rs[i] = s;
        }
#pragma unroll
        for (int i = 0; i < 4; i++) l[i] += rs[i];

#pragma unroll
        for (int i = 0; i < 4; i++) {
            float4 p4;
            p4.x = sc[i][0]; p4.y = sc[i][1]; p4.z = sc[i][2]; p4.w = sc[i][3];
            *(float4*)(Ps + (ty * 4 + i) * 68 + tx * 4) = p4;
        }
        __syncthreads();

#pragma unroll 16
        for (int k = 0; k < 64; k++) {
            const float a0 = Ps[(ty * 4 + 0) * 68 + k];
            const float a1 = Ps[(ty * 4 + 1) * 68 + k];
            const float a2 = Ps[(ty * 4 + 2) * 68 + k];
            const float a3 = Ps[(ty * 4 + 3) * 68 + k];
            float b4[4];
            *(float4*)b4 = *(float4*)(Vs + k * 68 + tx * 4);
#pragma unroll
            for (int j = 0; j < 4; j++) {
                o[0][j] += a0 * b4[j];
                o[1][j] += a1 * b4[j];
                o[2][j] += a2 * b4[j];
                o[3][j] += a3 * b4[j];
            }
        }
        __syncthreads();
    }

#pragma unroll
    for (int i = 0; i < 4; i++) {
        const float inv = 1.f / l[i];
        const int q = q0 + ty * 4 + i;
        float v0 = o[i][0] * inv, v1 = o[i][1] * inv;
        float v2 = o[i][2] * inv, v3 = o[i][3] * inv;
        const size_t idx = ((size_t)(b * SEQ + q)) * DIM + h * HD + tx * 4;
        __nv_bfloat162 h01, h23, l01, l23;
        h01.x = __float2bfloat16(v0); h01.y = __float2bfloat16(v1);
        h23.x = __float2bfloat16(v2); h23.y = __float2bfloat16(v3);
        l01.x = __float2bfloat16(v0 - __bfloat162float(h01.x));
        l01.y = __float2bfloat16(v1 - __bfloat162float(h01.y));
        l23.x = __float2bfloat16(v2 - __bfloat162float(h23.x));
        l23.y = __float2bfloat16(v3 - __bfloat162float(h23.y));
        *(__nv_bfloat162*)(g_AOhi + idx)     = h01;
        *(__nv_bfloat162*)(g_AOhi + idx + 2) = h23;
        *(__nv_bfloat162*)(g_AOlo + idx)     = l01;
        *(__nv_bfloat162*)(g_AOlo + idx + 2) = l23;
    }
}

// ---------------------------------------------------------------------------
extern "C" void kernel_launch(void* const* d_in, const int* in_sizes, int n_in,
                              void* d_out, int out_size)
{
    const float* x     = (const float*)d_in[0];
    const float* mask  = (const float*)d_in[1];
    const float* bias  = (const float*)d_in[2];
    const float* Wqkv  = (const float*)d_in[3];
    const float* bqkv  = (const float*)d_in[4];
    const float* Wout  = (const float*)d_in[5];
    const float* bout  = (const float*)d_in[6];
    float* out = (float*)d_out;

    cudaFuncSetAttribute(attn_kernel,
                         cudaFuncAttributeMaxDynamicSharedMemorySize, ATTN_SMEM);
    cudaFuncSetAttribute(mma_gemm_kernel,
                         cudaFuncAttributeMaxDynamicSharedMemorySize, GEMM_SMEM);

    __nv_bfloat16 *xhi, *xlo, *w1hi, *w1lo, *w2hi, *w2lo, *aohi, *aolo;
    cudaGetSymbolAddress((void**)&xhi,  g_Xhi);
    cudaGetSymbolAddress((void**)&xlo,  g_Xlo);
    cudaGetSymbolAddress((void**)&w1hi, g_W1hi);
    cudaGetSymbolAddress((void**)&w1lo, g_W1lo);
    cudaGetSymbolAddress((void**)&w2hi, g_W2hi);
    cudaGetSymbolAddress((void**)&w2lo, g_W2lo);
    cudaGetSymbolAddress((void**)&aohi, g_AOhi);
    cudaGetSymbolAddress((void**)&aolo, g_AOlo);

    // input conversions
    conv_split_kernel<<<(MROWS * DIM / 4 + 255) / 256, 256>>>(x, xhi, xlo,
                                                              MROWS * DIM / 4);
    conv_transpose_kernel<<<dim3(DIM / 32, QKVN / 32), dim3(32, 8)>>>(
        Wqkv, w1hi, w1lo, DIM, QKVN);
    conv_transpose_kernel<<<dim3(DIM / 32, DIM / 32), dim3(32, 8)>>>(
        Wout, w2hi, w2lo, DIM, DIM);

    // QKV projection (HMMA bf16 split)
    mma_gemm_kernel<<<dim3(QKVN / 128, MROWS / 128), 256, GEMM_SMEM>>>(
        xhi, xlo, w1hi, w1lo, bqkv, nullptr, 1);

    // attention (fp32)
    attn_kernel<<<dim3(SEQ / 64, BATCH * NH), 256, ATTN_SMEM>>>(mask, bias);

    // output projection (HMMA bf16 split)
    mma_gemm_kernel<<<dim3(DIM / 128, MROWS / 128), 256, GEMM_SMEM>>>(
        aohi, aolo, w2hi, w2lo, bout, out, 0);
}

// round 4
// speedup vs baseline: 2.5383x; 1.7419x over previous
#include <cuda_runtime.h>
#include <cuda_bf16.h>

#define BATCH 2
#define SEQ   2048
#define DIM   1024
#define NH    16
#define HD    64
#define MROWS (BATCH*SEQ)   // 4096
#define QKVN  (3*DIM)       // 3072
#define LOG2E 1.4426950408889634f

// ---------------- scratch (__device__ globals; no runtime allocs) ----------
__device__ __nv_bfloat16 g_Qhi[(size_t)BATCH*NH*SEQ*HD];
__device__ __nv_bfloat16 g_Qlo[(size_t)BATCH*NH*SEQ*HD];
__device__ __nv_bfloat16 g_Khi[(size_t)BATCH*NH*SEQ*HD];
__device__ __nv_bfloat16 g_Klo[(size_t)BATCH*NH*SEQ*HD];
__device__ __nv_bfloat16 g_Vhi[(size_t)BATCH*NH*SEQ*HD];
__device__ __nv_bfloat16 g_Vlo[(size_t)BATCH*NH*SEQ*HD];
__device__ __nv_bfloat16 g_Xhi[(size_t)MROWS*DIM];
__device__ __nv_bfloat16 g_Xlo[(size_t)MROWS*DIM];
__device__ __nv_bfloat16 g_W1hi[(size_t)QKVN*DIM];   // Wqkv^T [3072][1024]
__device__ __nv_bfloat16 g_W1lo[(size_t)QKVN*DIM];
__device__ __nv_bfloat16 g_W2hi[(size_t)DIM*DIM];    // Wout^T [1024][1024]
__device__ __nv_bfloat16 g_W2lo[(size_t)DIM*DIM];
__device__ __nv_bfloat16 g_AOhi[(size_t)MROWS*DIM];  // attention out hi/lo
__device__ __nv_bfloat16 g_AOlo[(size_t)MROWS*DIM];
__device__ float g_MB[(size_t)BATCH*SEQ*SEQ];        // mask + bias combined

// ---------------- helpers ---------------------------------------------------
__device__ __forceinline__ unsigned smem_u32(const void* p) {
    unsigned a;
    asm("{ .reg .u64 t; cvta.to.shared.u64 t, %1; cvt.u32.u64 %0, t; }"
        : "=r"(a) : "l"(p));
    return a;
}
__device__ __forceinline__ void ldsm4(unsigned& r0, unsigned& r1,
                                      unsigned& r2, unsigned& r3, unsigned a) {
    asm volatile("ldmatrix.sync.aligned.m8n8.x4.shared.b16 {%0,%1,%2,%3}, [%4];"
                 : "=r"(r0), "=r"(r1), "=r"(r2), "=r"(r3) : "r"(a));
}
__device__ __forceinline__ void ldsm4t(unsigned& r0, unsigned& r1,
                                       unsigned& r2, unsigned& r3, unsigned a) {
    asm volatile("ldmatrix.sync.aligned.m8n8.x4.trans.shared.b16 {%0,%1,%2,%3}, [%4];"
                 : "=r"(r0), "=r"(r1), "=r"(r2), "=r"(r3) : "r"(a));
}
__device__ __forceinline__ void mma_bf16(float* c, const unsigned* a,
                                         unsigned b0, unsigned b1) {
    asm volatile(
        "mma.sync.aligned.m16n8k16.row.col.f32.bf16.bf16.f32 "
        "{%0,%1,%2,%3}, {%4,%5,%6,%7}, {%8,%9}, {%0,%1,%2,%3};"
        : "+f"(c[0]), "+f"(c[1]), "+f"(c[2]), "+f"(c[3])
        : "r"(a[0]), "r"(a[1]), "r"(a[2]), "r"(a[3]), "r"(b0), "r"(b1));
}
__device__ __forceinline__ void cp16(unsigned dst, const void* src) {
    asm volatile("cp.async.cg.shared.global [%0], [%1], 16;"
                 :: "r"(dst), "l"(src) : "memory");
}
__device__ __forceinline__ void cp_commit() {
    asm volatile("cp.async.commit_group;" ::: "memory");
}
// split a pair of floats into bf16x2 hi and lo (residual) packed registers
__device__ __forceinline__ void split2(float a, float b, unsigned& hi, unsigned& lo) {
    float ha = __bfloat162float(__float2bfloat16(a));
    float hb = __bfloat162float(__float2bfloat16(b));
    asm("cvt.rn.bf16x2.f32 %0, %1, %2;" : "=r"(hi) : "f"(hb), "f"(ha));
    asm("cvt.rn.bf16x2.f32 %0, %1, %2;" : "=r"(lo) : "f"(b - hb), "f"(a - ha));
}
__device__ __forceinline__ unsigned packbf(float a, float b) {
    unsigned r;
    asm("cvt.rn.bf16x2.f32 %0, %1, %2;" : "=r"(r) : "f"(b), "f"(a));
    return r;
}
// fast 2^t on the FMA pipe (t <= 0, clamped; ~2e-6 rel err)
__device__ __forceinline__ float fexp2(float t) {
    t = fmaxf(t, -100.f);
    float fi = rintf(t);
    float f = t - fi;
    float p = 1.3333558e-3f;
    p = fmaf(p, f, 9.6181291e-3f);
    p = fmaf(p, f, 5.5504109e-2f);
    p = fmaf(p, f, 2.4022651e-1f);
    p = fmaf(p, f, 6.9314718e-1f);
    p = fmaf(p, f, 1.0f);
    return __int_as_float(__float_as_int(p) + (((int)fi) << 23));
}

#define GEMM_SMEM (2*65536)

// ---------------------------------------------------------------------------
// conversions
// ---------------------------------------------------------------------------
__global__ __launch_bounds__(256) void conv_split_kernel(
    const float* __restrict__ src, __nv_bfloat16* __restrict__ hi,
    __nv_bfloat16* __restrict__ lo, int n4)
{
    int i = blockIdx.x * 256 + threadIdx.x;
    if (i >= n4) return;
    float4 v = *((const float4*)src + i);
    unsigned h01, h23, l01, l23;
    split2(v.x, v.y, h01, l01);
    split2(v.z, v.w, h23, l23);
    ((unsigned*)hi)[i*2+0] = h01;
    ((unsigned*)hi)[i*2+1] = h23;
    ((unsigned*)lo)[i*2+0] = l01;
    ((unsigned*)lo)[i*2+1] = l23;
}

__global__ void conv_transpose_kernel(
    const float* __restrict__ W, __nv_bfloat16* __restrict__ Thi,
    __nv_bfloat16* __restrict__ Tlo, int K, int N)
{
    __shared__ float t[32][33];
    const int k0 = blockIdx.x * 32, n0 = blockIdx.y * 32;
    const int tx = threadIdx.x, ty = threadIdx.y;
    for (int i = ty; i < 32; i += 8)
        t[i][tx] = W[(size_t)(k0 + i) * N + n0 + tx];
    __syncthreads();
    for (int i = ty; i < 32; i += 8) {
        float v = t[tx][i];
        __nv_bfloat16 h = __float2bfloat16(v);
        Thi[(size_t)(n0 + i) * K + k0 + tx] = h;
        Tlo[(size_t)(n0 + i) * K + k0 + tx] =
            __float2bfloat16(v - __bfloat162float(h));
    }
}

// combined mask+bias: g_MB[b][q][k] = mask[q][k] + bias[b][q][k]
__global__ __launch_bounds__(256) void mb_kernel(
    const float* __restrict__ mask, const float* __restrict__ bias, int n4)
{
    int i = blockIdx.x * 256 + threadIdx.x;
    if (i >= n4) return;
    const int per_b = SEQ * SEQ / 4;
    int r = i % per_b;
    float4 mk = ((const float4*)mask)[r];
    float4 bs = ((const float4*)bias)[i];
    float4 o;
    o.x = mk.x + bs.x; o.y = mk.y + bs.y;
    o.z = mk.z + bs.z; o.w = mk.w + bs.w;
    ((float4*)g_MB)[i] = o;
}

// ---------------------------------------------------------------------------
// HMMA split-bf16 GEMM (as round 3). mode 0: out fp32. mode 1: emit Q/K/V
// as bf16 hi/lo (Q pre-scaled by 0.125).
// ---------------------------------------------------------------------------
__global__ __launch_bounds__(256) void mma_gemm_kernel(
    const __nv_bfloat16* __restrict__ Ahi, const __nv_bfloat16* __restrict__ Alo,
    const __nv_bfloat16* __restrict__ Bhi, const __nv_bfloat16* __restrict__ Blo,
    const float* __restrict__ bias, float* __restrict__ out, int mode)
{
    extern __shared__ char smraw[];
    const unsigned sbase = smem_u32(smraw);
    const int tid  = threadIdx.x;
    const int wid  = tid >> 5;
    const int lane = tid & 31;
    const int warp_m = wid & 3;
    const int warp_n = wid >> 2;
    const int row_a = blockIdx.y * 128;
    const int col0  = blockIdx.x * 128;

    float acc[2][8][4];
#pragma unroll
    for (int i = 0; i < 2; i++)
#pragma unroll
        for (int j = 0; j < 8; j++)
#pragma unroll
            for (int c = 0; c < 4; c++) acc[i][j][c] = 0.f;

    auto issue = [&](int t) {
        const int k0 = t * 64;
        const unsigned stage = (unsigned)((t & 1) * 65536);
#pragma unroll
        for (int p = 0; p < 4; p++) {
            const __nv_bfloat16* src = (p == 0) ? Ahi : (p == 1) ? Alo
                                     : (p == 2) ? Bhi : Blo;
            const int rb = (p < 2) ? row_a : col0;
            const unsigned pb = stage + (unsigned)p * 16384u;
#pragma unroll
            for (int i = 0; i < 4; i++) {
                const int e = tid + i * 256;
                const int r = e >> 3, c4 = e & 7;
                unsigned off = (unsigned)(r * 128 + c4 * 16);
                off ^= (off >> 3) & 0x70;
                cp16(sbase + pb + off,
                     src + (size_t)(rb + r) * DIM + k0 + c4 * 8);
            }
        }
        cp_commit();
    };

    issue(0);
    issue(1);

    const int amat = lane >> 3;
    const int arow = warp_m * 32 + (lane & 7) + ((amat & 1) << 3);
    const unsigned acolx = (unsigned)((amat >> 1) << 4);
    const int brow = warp_n * 64 + (lane & 7) + ((amat >> 1) << 3);
    const unsigned bcolx = (unsigned)((amat & 1) << 4);

    for (int t = 0; t < 16; t++) {
        if (t < 15)
            asm volatile("cp.async.wait_group 1;" ::: "memory");
        else
            asm volatile("cp.async.wait_group 0;" ::: "memory");
        __syncthreads();

        const unsigned stage = (unsigned)((t & 1) * 65536);
#pragma unroll
        for (int ks = 0; ks < 4; ks++) {
            const unsigned kb = (unsigned)(ks * 32);
            unsigned ah[2][4], al[2][4], bh[4][4], bl[4][4];
#pragma unroll
            for (int mf = 0; mf < 2; mf++) {
                const int r = arow + mf * 16;
                const unsigned ro = (unsigned)(r * 128) + ((kb + acolx) ^ (((unsigned)(r & 7)) << 4));
                ldsm4(ah[mf][0], ah[mf][1], ah[mf][2], ah[mf][3], sbase + stage + ro);
                ldsm4(al[mf][0], al[mf][1], al[mf][2], al[mf][3], sbase + stage + 16384 + ro);
            }
#pragma unroll
            for (int np = 0; np < 4; np++) {
                const int r = brow + np * 16;
                const unsigned ro = (unsigned)(r * 128) + ((kb + bcolx) ^ (((unsigned)(r & 7)) << 4));
                ldsm4(bh[np][0], bh[np][1], bh[np][2], bh[np][3], sbase + stage + 32768 + ro);
                ldsm4(bl[np][0], bl[np][1], bl[np][2], bl[np][3], sbase + stage + 49152 + ro);
            }
#pragma unroll
            for (int mf = 0; mf < 2; mf++) {
#pragma unroll
                for (int nn = 0; nn < 8; nn++) {
                    const int np = nn >> 1, hf = (nn & 1) * 2;
                    mma_bf16(acc[mf][nn], ah[mf], bh[np][hf], bh[np][hf + 1]);
                    mma_bf16(acc[mf][nn], ah[mf], bl[np][hf], bl[np][hf + 1]);
                    mma_bf16(acc[mf][nn], al[mf], bh[np][hf], bh[np][hf + 1]);
                }
            }
        }
        if (t + 2 < 16) {
            __syncthreads();
            issue(t + 2);
        }
    }

#pragma unroll
    for (int mf = 0; mf < 2; mf++) {
#pragma unroll
        for (int nn = 0; nn < 8; nn++) {
            const int gc = col0 + warp_n * 64 + nn * 8 + (lane & 3) * 2;
            const int r0 = row_a + warp_m * 32 + mf * 16 + (lane >> 2);
            const float bx = bias[gc], by = bias[gc + 1];
            float2 v0, v1;
            v0.x = acc[mf][nn][0] + bx; v0.y = acc[mf][nn][1] + by;
            v1.x = acc[mf][nn][2] + bx; v1.y = acc[mf][nn][3] + by;
            if (mode == 0) {
                *(float2*)(out + (size_t)r0 * DIM + gc)       = v0;
                *(float2*)(out + (size_t)(r0 + 8) * DIM + gc) = v1;
            } else {
                const int sel = gc >> 10;
                const int w   = gc & 1023;
                const int h   = w >> 6;
                const int d0  = w & 63;
                __nv_bfloat16 *dh, *dl;
                float sc;
                if (sel == 0)      { dh = g_Qhi; dl = g_Qlo; sc = 0.125f; }
                else if (sel == 1) { dh = g_Khi; dl = g_Klo; sc = 1.f; }
                else               { dh = g_Vhi; dl = g_Vlo; sc = 1.f; }
                v0.x *= sc; v0.y *= sc; v1.x *= sc; v1.y *= sc;
                const int b0 = r0 >> 11, s0 = r0 & 2047;
                const int r1 = r0 + 8;
                const int b1 = r1 >> 11, s1 = r1 & 2047;
                const size_t i0 = (((size_t)b0 * NH + h) * SEQ + s0) * HD + d0;
                const size_t i1 = (((size_t)b1 * NH + h) * SEQ + s1) * HD + d0;
                unsigned h0, l0, h1, l1;
                split2(v0.x, v0.y, h0, l0);
                split2(v1.x, v1.y, h1, l1);
                *(unsigned*)(dh + i0) = h0; *(unsigned*)(dl + i0) = l0;
                *(unsigned*)(dh + i1) = h1; *(unsigned*)(dl + i1) = l1;
            }
        }
    }
}

// ---------------------------------------------------------------------------
// Tensor-core flash attention: 128 q-rows x 64-key tiles, 8 warps x 16 rows.
// Split-bf16 (3 MMAs) for both QK^T and P.V; software exp2; fp32 mask+bias.
// ---------------------------------------------------------------------------
#define ATTN_SMEM (32768 + 2*32768)    // Qhi|Qlo + 2 stages of (Khi|Klo|Vhi|Vlo)

__global__ __launch_bounds__(256) void attn_mma_kernel()
{
    extern __shared__ char smraw[];
    const unsigned sbase = smem_u32(smraw);
    const int tid = threadIdx.x, wid = tid >> 5, lane = tid & 31;
    const int bh = blockIdx.y, b = bh >> 4, h = bh & 15;
    const int q0 = blockIdx.x * 128;

    const __nv_bfloat16* Qh = g_Qhi + (size_t)bh * SEQ * HD;
    const __nv_bfloat16* Ql = g_Qlo + (size_t)bh * SEQ * HD;
    const __nv_bfloat16* Kh = g_Khi + (size_t)bh * SEQ * HD;
    const __nv_bfloat16* Kl = g_Klo + (size_t)bh * SEQ * HD;
    const __nv_bfloat16* Vh = g_Vhi + (size_t)bh * SEQ * HD;
    const __nv_bfloat16* Vl = g_Vlo + (size_t)bh * SEQ * HD;

    // Q tiles -> smem (async, own group)
#pragma unroll
    for (int p = 0; p < 2; p++) {
        const __nv_bfloat16* src = p ? Ql : Qh;
#pragma unroll
        for (int i = 0; i < 4; i++) {
            const int e = tid + i * 256;          // 0..1023
            const int r = e >> 3, c4 = e & 7;
            unsigned off = (unsigned)(r * 128 + c4 * 16);
            off ^= (off >> 3) & 0x70;
            cp16(sbase + (unsigned)p * 16384u + off,
                 src + (size_t)(q0 + r) * HD + c4 * 8);
        }
    }
    cp_commit();

    auto issue = [&](int t) {
        const int k0 = t * 64;
        const unsigned stg = 32768u + (unsigned)((t & 1) * 32768);
#pragma unroll
        for (int p = 0; p < 4; p++) {
            const __nv_bfloat16* src = (p == 0) ? Kh : (p == 1) ? Kl
                                     : (p == 2) ? Vh : Vl;
#pragma unroll
            for (int i = 0; i < 2; i++) {
                const int e = tid + i * 256;       // 0..511
                const int r = e >> 3, c4 = e & 7;
                unsigned off = (unsigned)(r * 128 + c4 * 16);
                off ^= (off >> 3) & 0x70;
                cp16(sbase + stg + (unsigned)p * 8192u + off,
                     src + (size_t)(k0 + r) * HD + c4 * 8);
            }
        }
        cp_commit();
    };
    issue(0);

    const int amat = lane >> 3;
    const int arow = wid * 16 + (lane & 7) + ((amat & 1) << 3);
    const unsigned acolx = (unsigned)((amat >> 1) << 4);
    const int krow_b = (lane & 7) + ((amat >> 1) << 3);
    const unsigned kcolx = (unsigned)((amat & 1) << 4);
    const int vrow_b = (lane & 7) + ((amat & 1) << 3);
    const unsigned vcolb = (unsigned)((lane >> 4) << 4);

    const float* mbp = g_MB + ((size_t)b * SEQ + q0 + wid * 16 + (lane >> 2)) * SEQ
                       + (lane & 3) * 2;

    unsigned qh[4][4], ql[4][4];
    float o[8][4];
#pragma unroll
    for (int nn = 0; nn < 8; nn++)
#pragma unroll
        for (int c = 0; c < 4; c++) o[nn][c] = 0.f;
    float sM0 = -1e30f, sM1 = -1e30f, sL0 = 0.f, sL1 = 0.f;

    for (int t = 0; t < 32; t++) {
        if (t + 1 < 32) {
            issue(t + 1);
            asm volatile("cp.async.wait_group 1;" ::: "memory");
        } else {
            asm volatile("cp.async.wait_group 0;" ::: "memory");
        }
        __syncthreads();
        const unsigned stg = sbase + 32768u + (unsigned)((t & 1) * 32768);

        if (t == 0) {
#pragma unroll
            for (int ks = 0; ks < 4; ks++) {
                unsigned off = (unsigned)(arow * 128)
                             + (((unsigned)(ks * 32) + acolx) ^ (((unsigned)(arow & 7)) << 4));
                ldsm4(qh[ks][0], qh[ks][1], qh[ks][2], qh[ks][3], sbase + off);
                ldsm4(ql[ks][0], ql[ks][1], ql[ks][2], ql[ks][3], sbase + 16384 + off);
            }
        }

        // ---- S = Q.K^T (split bf16) ----
        float s[8][4];
#pragma unroll
        for (int nn = 0; nn < 8; nn++)
#pragma unroll
            for (int c = 0; c < 4; c++) s[nn][c] = 0.f;
#pragma unroll
        for (int ks = 0; ks < 4; ks++) {
#pragma unroll
            for (int np = 0; np < 4; np++) {
                const int kr = np * 16 + krow_b;
                unsigned off = (unsigned)(kr * 128)
                             + (((unsigned)(ks * 32) + kcolx) ^ (((unsigned)(kr & 7)) << 4));
                unsigned khf[4], klf[4];
                ldsm4(khf[0], khf[1], khf[2], khf[3], stg + off);
                ldsm4(klf[0], klf[1], klf[2], klf[3], stg + 8192 + off);
                mma_bf16(s[2*np],   qh[ks], khf[0], khf[1]);
                mma_bf16(s[2*np],   qh[ks], klf[0], klf[1]);
                mma_bf16(s[2*np],   ql[ks], khf[0], khf[1]);
                mma_bf16(s[2*np+1], qh[ks], khf[2], khf[3]);
                mma_bf16(s[2*np+1], qh[ks], klf[2], klf[3]);
                mma_bf16(s[2*np+1], ql[ks], khf[2], khf[3]);
            }
        }

        // ---- + mask + bias ----
        const float* mrow = mbp + t * 64;
#pragma unroll
        for (int nn = 0; nn < 8; nn++) {
            float2 u0 = *(const float2*)(mrow + nn * 8);
            float2 u1 = *(const float2*)(mrow + 8 * SEQ + nn * 8);
            s[nn][0] += u0.x; s[nn][1] += u0.y;
            s[nn][2] += u1.x; s[nn][3] += u1.y;
        }

        // ---- online softmax (2 rows/thread) ----
        float mx0 = -1e30f, mx1 = -1e30f;
#pragma unroll
        for (int nn = 0; nn < 8; nn++) {
            mx0 = fmaxf(mx0, fmaxf(s[nn][0], s[nn][1]));
            mx1 = fmaxf(mx1, fmaxf(s[nn][2], s[nn][3]));
        }
        mx0 = fmaxf(mx0, __shfl_xor_sync(0xffffffffu, mx0, 1));
        mx0 = fmaxf(mx0, __shfl_xor_sync(0xffffffffu, mx0, 2));
        mx1 = fmaxf(mx1, __shfl_xor_sync(0xffffffffu, mx1, 1));
        mx1 = fmaxf(mx1, __shfl_xor_sync(0xffffffffu, mx1, 2));
        const float mn0 = fmaxf(sM0, mx0), mn1 = fmaxf(sM1, mx1);
        const float c0 = fexp2((sM0 - mn0) * LOG2E);
        const float c1 = fexp2((sM1 - mn1) * LOG2E);
        sM0 = mn0; sM1 = mn1;
        float sum0 = 0.f, sum1 = 0.f;
#pragma unroll
        for (int nn = 0; nn < 8; nn++) {
            s[nn][0] = fexp2((s[nn][0] - mn0) * LOG2E); sum0 += s[nn][0];
            s[nn][1] = fexp2((s[nn][1] - mn0) * LOG2E); sum0 += s[nn][1];
            s[nn][2] = fexp2((s[nn][2] - mn1) * LOG2E); sum1 += s[nn][2];
            s[nn][3] = fexp2((s[nn][3] - mn1) * LOG2E); sum1 += s[nn][3];
        }
        sum0 += __shfl_xor_sync(0xffffffffu, sum0, 1);
        sum0 += __shfl_xor_sync(0xffffffffu, sum0, 2);
        sum1 += __shfl_xor_sync(0xffffffffu, sum1, 1);
        sum1 += __shfl_xor_sync(0xffffffffu, sum1, 2);
        sL0 = sL0 * c0 + sum0;
        sL1 = sL1 * c1 + sum1;
#pragma unroll
        for (int nn = 0; nn < 8; nn++) {
            o[nn][0] *= c0; o[nn][1] *= c0;
            o[nn][2] *= c1; o[nn][3] *= c1;
        }

        // ---- O += P.V (split bf16) ----
#pragma unroll
        for (int ks = 0; ks < 4; ks++) {
            unsigned pah[4], pal[4];
            split2(s[2*ks][0],   s[2*ks][1],   pah[0], pal[0]);
            split2(s[2*ks][2],   s[2*ks][3],   pah[1], pal[1]);
            split2(s[2*ks+1][0], s[2*ks+1][1], pah[2], pal[2]);
            split2(s[2*ks+1][2], s[2*ks+1][3], pah[3], pal[3]);
#pragma unroll
            for (int np = 0; np < 4; np++) {
                const int vr = ks * 16 + vrow_b;
                unsigned off = (unsigned)(vr * 128)
                             + (((unsigned)(np * 32) + vcolb) ^ (((unsigned)(vr & 7)) << 4));
                unsigned vhf[4], vlf[4];
                ldsm4t(vhf[0], vhf[1], vhf[2], vhf[3], stg + 16384 + off);
                ldsm4t(vlf[0], vlf[1], vlf[2], vlf[3], stg + 24576 + off);
                mma_bf16(o[2*np],   pah, vhf[0], vhf[1]);
                mma_bf16(o[2*np],   pah, vlf[0], vlf[1]);
                mma_bf16(o[2*np],   pal, vhf[0], vhf[1]);
                mma_bf16(o[2*np+1], pah, vhf[2], vhf[3]);
                mma_bf16(o[2*np+1], pah, vlf[2], vlf[3]);
                mma_bf16(o[2*np+1], pal, vhf[2], vhf[3]);
            }
        }
        __syncthreads();
    }

    // ---- normalize + emit bf16 hi/lo into g_AO ----
    const float inv0 = 1.f / sL0, inv1 = 1.f / sL1;
    const int qr = q0 + wid * 16 + (lane >> 2);
    const size_t base0 = ((size_t)(b * SEQ + qr)) * DIM + h * HD;
    const size_t base1 = base0 + (size_t)8 * DIM;
#pragma unroll
    for (int nn = 0; nn < 8; nn++) {
        const int c = nn * 8 + (lane & 3) * 2;
        unsigned hv, lv;
        split2(o[nn][0] * inv0, o[nn][1] * inv0, hv, lv);
        *(unsigned*)(g_AOhi + base0 + c) = hv;
        *(unsigned*)(g_AOlo + base0 + c) = lv;
        split2(o[nn][2] * inv1, o[nn][3] * inv1, hv, lv);
        *(unsigned*)(g_AOhi + base1 + c) = hv;
        *(unsigned*)(g_AOlo + base1 + c) = lv;
    }
}

// ---------------------------------------------------------------------------
extern "C" void kernel_launch(void* const* d_in, const int* in_sizes, int n_in,
                              void* d_out, int out_size)
{
    const float* x     = (const float*)d_in[0];
    const float* mask  = (const float*)d_in[1];
    const float* bias  = (const float*)d_in[2];
    const float* Wqkv  = (const float*)d_in[3];
    const float* bqkv  = (const float*)d_in[4];
    const float* Wout  = (const float*)d_in[5];
    const float* bout  = (const float*)d_in[6];
    float* out = (float*)d_out;

    cudaFuncSetAttribute(mma_gemm_kernel,
                         cudaFuncAttributeMaxDynamicSharedMemorySize, GEMM_SMEM);
    cudaFuncSetAttribute(attn_mma_kernel,
                         cudaFuncAttributeMaxDynamicSharedMemorySize, ATTN_SMEM);

    __nv_bfloat16 *xhi, *xlo, *w1hi, *w1lo, *w2hi, *w2lo, *aohi, *aolo;
    cudaGetSymbolAddress((void**)&xhi,  g_Xhi);
    cudaGetSymbolAddress((void**)&xlo,  g_Xlo);
    cudaGetSymbolAddress((void**)&w1hi, g_W1hi);
    cudaGetSymbolAddress((void**)&w1lo, g_W1lo);
    cudaGetSymbolAddress((void**)&w2hi, g_W2hi);
    cudaGetSymbolAddress((void**)&w2lo, g_W2lo);
    cudaGetSymbolAddress((void**)&aohi, g_AOhi);
    cudaGetSymbolAddress((void**)&aolo, g_AOlo);

    conv_split_kernel<<<(MROWS * DIM / 4 + 255) / 256, 256>>>(x, xhi, xlo,
                                                              MROWS * DIM / 4);
    conv_transpose_kernel<<<dim3(DIM / 32, QKVN / 32), dim3(32, 8)>>>(
        Wqkv, w1hi, w1lo, DIM, QKVN);
    conv_transpose_kernel<<<dim3(DIM / 32, DIM / 32), dim3(32, 8)>>>(
        Wout, w2hi, w2lo, DIM, DIM);
    mb_kernel<<<(BATCH * SEQ * SEQ / 4 + 255) / 256, 256>>>(
        mask, bias, BATCH * SEQ * SEQ / 4);

    mma_gemm_kernel<<<dim3(QKVN / 128, MROWS / 128), 256, GEMM_SMEM>>>(
        xhi, xlo, w1hi, w1lo, bqkv, nullptr, 1);

    attn_mma_kernel<<<dim3(SEQ / 128, BATCH * NH), 256, ATTN_SMEM>>>();

    mma_gemm_kernel<<<dim3(DIM / 128, MROWS / 128), 256, GEMM_SMEM>>>(
        aohi, aolo, w2hi, w2lo, bout, out, 0);
}

// round 5
// speedup vs baseline: 2.7318x; 1.0762x over previous
#include <cuda_runtime.h>
#include <cuda_bf16.h>
#include <cuda_fp16.h>

#define BATCH 2
#define SEQ   2048
#define DIM   1024
#define NH    16
#define HD    64
#define MROWS (BATCH*SEQ)   // 4096
#define QKVN  (3*DIM)       // 3072
#define LOG2E 1.4426950408889634f

// ---------------- scratch (__device__ globals; no runtime allocs) ----------
__device__ __nv_bfloat16 g_Qhi[(size_t)BATCH*NH*SEQ*HD];
__device__ __nv_bfloat16 g_Qlo[(size_t)BATCH*NH*SEQ*HD];
__device__ __nv_bfloat16 g_Khi[(size_t)BATCH*NH*SEQ*HD];
__device__ __nv_bfloat16 g_Klo[(size_t)BATCH*NH*SEQ*HD];
__device__ __nv_bfloat16 g_Vhi[(size_t)BATCH*NH*SEQ*HD];
__device__ __nv_bfloat16 g_Vlo[(size_t)BATCH*NH*SEQ*HD];
__device__ __nv_bfloat16 g_Xhi[(size_t)MROWS*DIM];
__device__ __nv_bfloat16 g_Xlo[(size_t)MROWS*DIM];
__device__ __nv_bfloat16 g_W1hi[(size_t)QKVN*DIM];   // Wqkv^T [3072][1024]
__device__ __nv_bfloat16 g_W1lo[(size_t)QKVN*DIM];
__device__ __nv_bfloat16 g_W2hi[(size_t)DIM*DIM];    // Wout^T [1024][1024]
__device__ __nv_bfloat16 g_W2lo[(size_t)DIM*DIM];
__device__ __nv_bfloat16 g_AOhi[(size_t)MROWS*DIM];  // attention out hi/lo
__device__ __nv_bfloat16 g_AOlo[(size_t)MROWS*DIM];
__device__ __half g_MB[(size_t)BATCH*SEQ*SEQ];       // mask + bias (fp16)

// ---------------- helpers ---------------------------------------------------
__device__ __forceinline__ unsigned smem_u32(const void* p) {
    unsigned a;
    asm("{ .reg .u64 t; cvta.to.shared.u64 t, %1; cvt.u32.u64 %0, t; }"
        : "=r"(a) : "l"(p));
    return a;
}
__device__ __forceinline__ void ldsm4(unsigned& r0, unsigned& r1,
                                      unsigned& r2, unsigned& r3, unsigned a) {
    asm volatile("ldmatrix.sync.aligned.m8n8.x4.shared.b16 {%0,%1,%2,%3}, [%4];"
                 : "=r"(r0), "=r"(r1), "=r"(r2), "=r"(r3) : "r"(a));
}
__device__ __forceinline__ void ldsm4t(unsigned& r0, unsigned& r1,
                                       unsigned& r2, unsigned& r3, unsigned a) {
    asm volatile("ldmatrix.sync.aligned.m8n8.x4.trans.shared.b16 {%0,%1,%2,%3}, [%4];"
                 : "=r"(r0), "=r"(r1), "=r"(r2), "=r"(r3) : "r"(a));
}
__device__ __forceinline__ void mma_bf16(float* c, const unsigned* a,
                                         unsigned b0, unsigned b1) {
    asm volatile(
        "mma.sync.aligned.m16n8k16.row.col.f32.bf16.bf16.f32 "
        "{%0,%1,%2,%3}, {%4,%5,%6,%7}, {%8,%9}, {%0,%1,%2,%3};"
        : "+f"(c[0]), "+f"(c[1]), "+f"(c[2]), "+f"(c[3])
        : "r"(a[0]), "r"(a[1]), "r"(a[2]), "r"(a[3]), "r"(b0), "r"(b1));
}
__device__ __forceinline__ void cp16(unsigned dst, const void* src) {
    asm volatile("cp.async.cg.shared.global [%0], [%1], 16;"
                 :: "r"(dst), "l"(src) : "memory");
}
__device__ __forceinline__ void cp_commit() {
    asm volatile("cp.async.commit_group;" ::: "memory");
}
__device__ __forceinline__ void split2(float a, float b, unsigned& hi, unsigned& lo) {
    float ha = __bfloat162float(__float2bfloat16(a));
    float hb = __bfloat162float(__float2bfloat16(b));
    asm("cvt.rn.bf16x2.f32 %0, %1, %2;" : "=r"(hi) : "f"(hb), "f"(ha));
    asm("cvt.rn.bf16x2.f32 %0, %1, %2;" : "=r"(lo) : "f"(b - hb), "f"(a - ha));
}
// fast 2^t on the FMA pipe (t <= 0, clamped; ~2e-6 rel err)
__device__ __forceinline__ float fexp2(float t) {
    t = fmaxf(t, -100.f);
    float fi = rintf(t);
    float f = t - fi;
    float p = 1.3333558e-3f;
    p = fmaf(p, f, 9.6181291e-3f);
    p = fmaf(p, f, 5.5504109e-2f);
    p = fmaf(p, f, 2.4022651e-1f);
    p = fmaf(p, f, 6.9314718e-1f);
    p = fmaf(p, f, 1.0f);
    return __int_as_float(__float_as_int(p) + (((int)fi) << 23));
}
// swizzled offset in a [rows][32 bf16] tile (64B rows)
__device__ __forceinline__ unsigned swz64(int row, unsigned colb) {
    return (unsigned)(row * 64) + (colb ^ (((unsigned)(row >> 1) & 3u) << 4));
}

#define GEMM_SMEM (3*32768)     // 3 stages x (Ahi|Alo|Bhi|Blo) 8KB tiles

// ---------------------------------------------------------------------------
// conversions
// ---------------------------------------------------------------------------
__global__ __launch_bounds__(256) void conv_split_kernel(
    const float* __restrict__ src, __nv_bfloat16* __restrict__ hi,
    __nv_bfloat16* __restrict__ lo, int n4)
{
    int i = blockIdx.x * 256 + threadIdx.x;
    if (i >= n4) return;
    float4 v = *((const float4*)src + i);
    unsigned h01, h23, l01, l23;
    split2(v.x, v.y, h01, l01);
    split2(v.z, v.w, h23, l23);
    ((unsigned*)hi)[i*2+0] = h01;
    ((unsigned*)hi)[i*2+1] = h23;
    ((unsigned*)lo)[i*2+0] = l01;
    ((unsigned*)lo)[i*2+1] = l23;
}

__global__ void conv_transpose_kernel(
    const float* __restrict__ W, __nv_bfloat16* __restrict__ Thi,
    __nv_bfloat16* __restrict__ Tlo, int K, int N)
{
    __shared__ float t[32][33];
    const int k0 = blockIdx.x * 32, n0 = blockIdx.y * 32;
    const int tx = threadIdx.x, ty = threadIdx.y;
    for (int i = ty; i < 32; i += 8)
        t[i][tx] = W[(size_t)(k0 + i) * N + n0 + tx];
    __syncthreads();
    for (int i = ty; i < 32; i += 8) {
        float v = t[tx][i];
        __nv_bfloat16 h = __float2bfloat16(v);
        Thi[(size_t)(n0 + i) * K + k0 + tx] = h;
        Tlo[(size_t)(n0 + i) * K + k0 + tx] =
            __float2bfloat16(v - __bfloat162float(h));
    }
}

// combined mask+bias in fp16: g_MB[b][q][k] = mask[q][k] + bias[b][q][k]
__global__ __launch_bounds__(256) void mb_kernel(
    const float* __restrict__ mask, const float* __restrict__ bias, int n8)
{
    int i = blockIdx.x * 256 + threadIdx.x;
    if (i >= n8) return;
    const int per_b = SEQ * SEQ / 8;
    int r = i % per_b;
    float4 m0 = ((const float4*)mask)[r*2+0];
    float4 m1 = ((const float4*)mask)[r*2+1];
    float4 b0 = ((const float4*)bias)[i*2+0];
    float4 b1 = ((const float4*)bias)[i*2+1];
    __half2 o[4];
    o[0] = __floats2half2_rn(m0.x + b0.x, m0.y + b0.y);
    o[1] = __floats2half2_rn(m0.z + b0.z, m0.w + b0.w);
    o[2] = __floats2half2_rn(m1.x + b1.x, m1.y + b1.y);
    o[3] = __floats2half2_rn(m1.z + b1.z, m1.w + b1.w);
    ((uint4*)g_MB)[i] = *(uint4*)o;
}

// ---------------------------------------------------------------------------
// HMMA split-bf16 GEMM. BK=32, 3-stage cp.async pipeline, 2 CTAs/SM.
// mode 0: out fp32 + bias. mode 1: emit Q/K/V bf16 hi/lo (Q scaled 0.125).
// ---------------------------------------------------------------------------
__global__ __launch_bounds__(256, 2) void mma_gemm_kernel(
    const __nv_bfloat16* __restrict__ Ahi, const __nv_bfloat16* __restrict__ Alo,
    const __nv_bfloat16* __restrict__ Bhi, const __nv_bfloat16* __restrict__ Blo,
    const float* __restrict__ bias, float* __restrict__ out, int mode)
{
    extern __shared__ char smraw[];
    const unsigned sbase = smem_u32(smraw);
    const int tid  = threadIdx.x;
    const int wid  = tid >> 5;
    const int lane = tid & 31;
    const int warp_m = wid & 3;
    const int warp_n = wid >> 2;
    const int row_a = blockIdx.y * 128;
    const int col0  = blockIdx.x * 128;

    float acc[2][8][4];
#pragma unroll
    for (int i = 0; i < 2; i++)
#pragma unroll
        for (int j = 0; j < 8; j++)
#pragma unroll
            for (int c = 0; c < 4; c++) acc[i][j][c] = 0.f;

    // stage layout: Ahi 0 | Alo 8192 | Bhi 16384 | Blo 24576
    auto issue = [&](int t) {
        const int k0 = t * 32;
        const unsigned stage = (unsigned)((t % 3) * 32768);
#pragma unroll
        for (int p = 0; p < 4; p++) {
            const __nv_bfloat16* src = (p == 0) ? Ahi : (p == 1) ? Alo
                                     : (p == 2) ? Bhi : Blo;
            const int rb = (p < 2) ? row_a : col0;
            const unsigned pb = stage + (unsigned)p * 8192u;
#pragma unroll
            for (int i = 0; i < 2; i++) {
                const int e = tid + i * 256;          // 0..511
                const int r = e >> 2, c16 = e & 3;
                cp16(sbase + pb + swz64(r, (unsigned)(c16 * 16)),
                     src + (size_t)(rb + r) * DIM + k0 + c16 * 8);
            }
        }
        cp_commit();
    };

    issue(0); issue(1); issue(2);

    const int amat = lane >> 3;
    const int arow_l = (lane & 7) + ((amat & 1) << 3);
    const unsigned acolx = (unsigned)((amat >> 1) << 4);
    const int brow_l = (lane & 7) + ((amat >> 1) << 3);
    const unsigned bcolx = (unsigned)((amat & 1) << 4);

    for (int t = 0; t < 32; t++) {
        if (t <= 29)      asm volatile("cp.async.wait_group 2;" ::: "memory");
        else if (t == 30) asm volatile("cp.async.wait_group 1;" ::: "memory");
        else              asm volatile("cp.async.wait_group 0;" ::: "memory");
        __syncthreads();

        const unsigned stage = sbase + (unsigned)((t % 3) * 32768);
#pragma unroll
        for (int ks = 0; ks < 2; ks++) {
            const unsigned kb = (unsigned)(ks * 32);
            unsigned bh[4][4], bl[4][4];
#pragma unroll
            for (int np = 0; np < 4; np++) {
                const int r = warp_n * 64 + np * 16 + brow_l;
                const unsigned ro = swz64(r, kb + bcolx);
                ldsm4(bh[np][0], bh[np][1], bh[np][2], bh[np][3], stage + 16384 + ro);
                ldsm4(bl[np][0], bl[np][1], bl[np][2], bl[np][3], stage + 24576 + ro);
            }
#pragma unroll
            for (int mf = 0; mf < 2; mf++) {
                const int r = warp_m * 32 + mf * 16 + arow_l;
                const unsigned ro = swz64(r, kb + acolx);
                unsigned ah[4], al[4];
                ldsm4(ah[0], ah[1], ah[2], ah[3], stage + ro);
                ldsm4(al[0], al[1], al[2], al[3], stage + 8192 + ro);
#pragma unroll
                for (int nn = 0; nn < 8; nn++) {
                    const int np = nn >> 1, hf = (nn & 1) * 2;
                    mma_bf16(acc[mf][nn], ah, bh[np][hf], bh[np][hf + 1]);
                    mma_bf16(acc[mf][nn], ah, bl[np][hf], bl[np][hf + 1]);
                    mma_bf16(acc[mf][nn], al, bh[np][hf], bh[np][hf + 1]);
                }
            }
        }
        __syncthreads();
        if (t + 3 < 32) issue(t + 3);
    }

#pragma unroll
    for (int mf = 0; mf < 2; mf++) {
#pragma unroll
        for (int nn = 0; nn < 8; nn++) {
            const int gc = col0 + warp_n * 64 + nn * 8 + (lane & 3) * 2;
            const int r0 = row_a + warp_m * 32 + mf * 16 + (lane >> 2);
            const float bx = bias[gc], by = bias[gc + 1];
            float2 v0, v1;
            v0.x = acc[mf][nn][0] + bx; v0.y = acc[mf][nn][1] + by;
            v1.x = acc[mf][nn][2] + bx; v1.y = acc[mf][nn][3] + by;
            if (mode == 0) {
                *(float2*)(out + (size_t)r0 * DIM + gc)       = v0;
                *(float2*)(out + (size_t)(r0 + 8) * DIM + gc) = v1;
            } else {
                const int sel = gc >> 10;
                const int w   = gc & 1023;
                const int h   = w >> 6;
                const int d0  = w & 63;
                __nv_bfloat16 *dh, *dl;
                float sc;
                if (sel == 0)      { dh = g_Qhi; dl = g_Qlo; sc = 0.125f; }
                else if (sel == 1) { dh = g_Khi; dl = g_Klo; sc = 1.f; }
                else               { dh = g_Vhi; dl = g_Vlo; sc = 1.f; }
                v0.x *= sc; v0.y *= sc; v1.x *= sc; v1.y *= sc;
                const int b0 = r0 >> 11, s0 = r0 & 2047;
                const int r1 = r0 + 8;
                const int b1 = r1 >> 11, s1 = r1 & 2047;
                const size_t i0 = (((size_t)b0 * NH + h) * SEQ + s0) * HD + d0;
                const size_t i1 = (((size_t)b1 * NH + h) * SEQ + s1) * HD + d0;
                unsigned h0, l0, h1, l1;
                split2(v0.x, v0.y, h0, l0);
                split2(v1.x, v1.y, h1, l1);
                *(unsigned*)(dh + i0) = h0; *(unsigned*)(dl + i0) = l0;
                *(unsigned*)(dh + i1) = h1; *(unsigned*)(dl + i1) = l1;
            }
        }
    }
}

// ---------------------------------------------------------------------------
// Tensor-core flash attention. 128 q x 64 k tiles, 8 warps, 2 CTAs/SM.
// Q fragments reloaded from smem each iteration to stay under 128 regs.
// ---------------------------------------------------------------------------
#define ATTN_SMEM (32768 + 2*32768)    // Qhi|Qlo + 2 stages of (Khi|Klo|Vhi|Vlo)

__global__ __launch_bounds__(256, 2) void attn_mma_kernel()
{
    extern __shared__ char smraw[];
    const unsigned sbase = smem_u32(smraw);
    const int tid = threadIdx.x, wid = tid >> 5, lane = tid & 31;
    const int bh = blockIdx.y, b = bh >> 4, h = bh & 15;
    const int q0 = blockIdx.x * 128;

    const __nv_bfloat16* Qh = g_Qhi + (size_t)bh * SEQ * HD;
    const __nv_bfloat16* Ql = g_Qlo + (size_t)bh * SEQ * HD;
    const __nv_bfloat16* Kh = g_Khi + (size_t)bh * SEQ * HD;
    const __nv_bfloat16* Kl = g_Klo + (size_t)bh * SEQ * HD;
    const __nv_bfloat16* Vh = g_Vhi + (size_t)bh * SEQ * HD;
    const __nv_bfloat16* Vl = g_Vlo + (size_t)bh * SEQ * HD;

    // Q tiles -> smem (128B rows, 128B-swizzle)
#pragma unroll
    for (int p = 0; p < 2; p++) {
        const __nv_bfloat16* src = p ? Ql : Qh;
#pragma unroll
        for (int i = 0; i < 4; i++) {
            const int e = tid + i * 256;
            const int r = e >> 3, c4 = e & 7;
            unsigned off = (unsigned)(r * 128 + c4 * 16);
            off ^= (off >> 3) & 0x70;
            cp16(sbase + (unsigned)p * 16384u + off,
                 src + (size_t)(q0 + r) * HD + c4 * 8);
        }
    }
    cp_commit();

    auto issue = [&](int t) {
        const int k0 = t * 64;
        const unsigned stg = 32768u + (unsigned)((t & 1) * 32768);
#pragma unroll
        for (int p = 0; p < 4; p++) {
            const __nv_bfloat16* src = (p == 0) ? Kh : (p == 1) ? Kl
                                     : (p == 2) ? Vh : Vl;
#pragma unroll
            for (int i = 0; i < 2; i++) {
                const int e = tid + i * 256;
                const int r = e >> 3, c4 = e & 7;
                unsigned off = (unsigned)(r * 128 + c4 * 16);
                off ^= (off >> 3) & 0x70;
                cp16(sbase + stg + (unsigned)p * 8192u + off,
                     src + (size_t)(k0 + r) * HD + c4 * 8);
            }
        }
        cp_commit();
    };
    issue(0);

    const int amat = lane >> 3;
    const int arow = wid * 16 + (lane & 7) + ((amat & 1) << 3);
    const unsigned acolx = (unsigned)((amat >> 1) << 4);
    const int krow_b = (lane & 7) + ((amat >> 1) << 3);
    const unsigned kcolx = (unsigned)((amat & 1) << 4);
    const int vrow_b = (lane & 7) + ((amat & 1) << 3);
    const unsigned vcolb = (unsigned)((lane >> 4) << 4);

    const __half* mbp = g_MB + ((size_t)b * SEQ + q0 + wid * 16 + (lane >> 2)) * SEQ
                        + (lane & 3) * 2;

    float o[8][4];
#pragma unroll
    for (int nn = 0; nn < 8; nn++)
#pragma unroll
        for (int c = 0; c < 4; c++) o[nn][c] = 0.f;
    float sM0 = -1e30f, sM1 = -1e30f, sL0 = 0.f, sL1 = 0.f;

    for (int t = 0; t < 32; t++) {
        if (t + 1 < 32) {
            issue(t + 1);
            asm volatile("cp.async.wait_group 1;" ::: "memory");
        } else {
            asm volatile("cp.async.wait_group 0;" ::: "memory");
        }
        __syncthreads();
        const unsigned stg = sbase + 32768u + (unsigned)((t & 1) * 32768);

        // ---- S = Q.K^T (split bf16, Q frags reloaded from smem) ----
        float s[8][4];
#pragma unroll
        for (int nn = 0; nn < 8; nn++)
#pragma unroll
            for (int c = 0; c < 4; c++) s[nn][c] = 0.f;
#pragma unroll
        for (int ks = 0; ks < 4; ks++) {
            unsigned qoff = (unsigned)(arow * 128)
                          + (((unsigned)(ks * 32) + acolx) ^ (((unsigned)(arow & 7)) << 4));
            unsigned qh[4], ql[4];
            ldsm4(qh[0], qh[1], qh[2], qh[3], sbase + qoff);
            ldsm4(ql[0], ql[1], ql[2], ql[3], sbase + 16384 + qoff);
#pragma unroll
            for (int np = 0; np < 4; np++) {
                const int kr = np * 16 + krow_b;
                unsigned off = (unsigned)(kr * 128)
                             + (((unsigned)(ks * 32) + kcolx) ^ (((unsigned)(kr & 7)) << 4));
                unsigned khf[4], klf[4];
                ldsm4(khf[0], khf[1], khf[2], khf[3], stg + off);
                ldsm4(klf[0], klf[1], klf[2], klf[3], stg + 8192 + off);
                mma_bf16(s[2*np],   qh, khf[0], khf[1]);
                mma_bf16(s[2*np],   qh, klf[0], klf[1]);
                mma_bf16(s[2*np],   ql, khf[0], khf[1]);
                mma_bf16(s[2*np+1], qh, khf[2], khf[3]);
                mma_bf16(s[2*np+1], qh, klf[2], klf[3]);
                mma_bf16(s[2*np+1], ql, khf[2], khf[3]);
            }
        }

        // ---- + mask + bias (fp16) ----
        const __half* mrow = mbp + t * 64;
#pragma unroll
        for (int nn = 0; nn < 8; nn++) {
            float2 f0 = __half22float2(*(const __half2*)(mrow + nn * 8));
            float2 f1 = __half22float2(*(const __half2*)(mrow + 8 * SEQ + nn * 8));
            s[nn][0] += f0.x; s[nn][1] += f0.y;
            s[nn][2] += f1.x; s[nn][3] += f1.y;
        }

        // ---- online softmax (2 rows/thread) ----
        float mx0 = -1e30f, mx1 = -1e30f;
#pragma unroll
        for (int nn = 0; nn < 8; nn++) {
            mx0 = fmaxf(mx0, fmaxf(s[nn][0], s[nn][1]));
            mx1 = fmaxf(mx1, fmaxf(s[nn][2], s[nn][3]));
        }
        mx0 = fmaxf(mx0, __shfl_xor_sync(0xffffffffu, mx0, 1));
        mx0 = fmaxf(mx0, __shfl_xor_sync(0xffffffffu, mx0, 2));
        mx1 = fmaxf(mx1, __shfl_xor_sync(0xffffffffu, mx1, 1));
        mx1 = fmaxf(mx1, __shfl_xor_sync(0xffffffffu, mx1, 2));
        const float mn0 = fmaxf(sM0, mx0), mn1 = fmaxf(sM1, mx1);
        const float c0 = fexp2((sM0 - mn0) * LOG2E);
        const float c1 = fexp2((sM1 - mn1) * LOG2E);
        sM0 = mn0; sM1 = mn1;
        float sum0 = 0.f, sum1 = 0.f;
#pragma unroll
        for (int nn = 0; nn < 8; nn++) {
            s[nn][0] = fexp2((s[nn][0] - mn0) * LOG2E); sum0 += s[nn][0];
            s[nn][1] = fexp2((s[nn][1] - mn0) * LOG2E); sum0 += s[nn][1];
            s[nn][2] = fexp2((s[nn][2] - mn1) * LOG2E); sum1 += s[nn][2];
            s[nn][3] = fexp2((s[nn][3] - mn1) * LOG2E); sum1 += s[nn][3];
        }
        sum0 += __shfl_xor_sync(0xffffffffu, sum0, 1);
        sum0 += __shfl_xor_sync(0xffffffffu, sum0, 2);
        sum1 += __shfl_xor_sync(0xffffffffu, sum1, 1);
        sum1 += __shfl_xor_sync(0xffffffffu, sum1, 2);
        sL0 = sL0 * c0 + sum0;
        sL1 = sL1 * c1 + sum1;
#pragma unroll
        for (int nn = 0; nn < 8; nn++) {
            o[nn][0] *= c0; o[nn][1] *= c0;
            o[nn][2] *= c1; o[nn][3] *= c1;
        }

        // ---- O += P.V (split bf16) ----
#pragma unroll
        for (int ks = 0; ks < 4; ks++) {
            unsigned pah[4], pal[4];
            split2(s[2*ks][0],   s[2*ks][1],   pah[0], pal[0]);
            split2(s[2*ks][2],   s[2*ks][3],   pah[1], pal[1]);
            split2(s[2*ks+1][0], s[2*ks+1][1], pah[2], pal[2]);
            split2(s[2*ks+1][2], s[2*ks+1][3], pah[3], pal[3]);
#pragma unroll
            for (int np = 0; np < 4; np++) {
                const int vr = ks * 16 + vrow_b;
                unsigned off = (unsigned)(vr * 128)
                             + (((unsigned)(np * 32) + vcolb) ^ (((unsigned)(vr & 7)) << 4));
                unsigned vhf[4], vlf[4];
                ldsm4t(vhf[0], vhf[1], vhf[2], vhf[3], stg + 16384 + off);
                ldsm4t(vlf[0], vlf[1], vlf[2], vlf[3], stg + 24576 + off);
                mma_bf16(o[2*np],   pah, vhf[0], vhf[1]);
                mma_bf16(o[2*np],   pah, vlf[0], vlf[1]);
                mma_bf16(o[2*np],   pal, vhf[0], vhf[1]);
                mma_bf16(o[2*np+1], pah, vhf[2], vhf[3]);
                mma_bf16(o[2*np+1], pah, vlf[2], vlf[3]);
                mma_bf16(o[2*np+1], pal, vhf[2], vhf[3]);
            }
        }
        __syncthreads();
    }

    // ---- normalize + emit bf16 hi/lo into g_AO ----
    const float inv0 = 1.f / sL0, inv1 = 1.f / sL1;
    const int qr = q0 + wid * 16 + (lane >> 2);
    const size_t base0 = ((size_t)(b * SEQ + qr)) * DIM + h * HD;
    const size_t base1 = base0 + (size_t)8 * DIM;
#pragma unroll
    for (int nn = 0; nn < 8; nn++) {
        const int c = nn * 8 + (lane & 3) * 2;
        unsigned hv, lv;
        split2(o[nn][0] * inv0, o[nn][1] * inv0, hv, lv);
        *(unsigned*)(g_AOhi + base0 + c) = hv;
        *(unsigned*)(g_AOlo + base0 + c) = lv;
        split2(o[nn][2] * inv1, o[nn][3] * inv1, hv, lv);
        *(unsigned*)(g_AOhi + base1 + c) = hv;
        *(unsigned*)(g_AOlo + base1 + c) = lv;
    }
}

// ---------------------------------------------------------------------------
extern "C" void kernel_launch(void* const* d_in, const int* in_sizes, int n_in,
                              void* d_out, int out_size)
{
    const float* x     = (const float*)d_in[0];
    const float* mask  = (const float*)d_in[1];
    const float* bias  = (const float*)d_in[2];
    const float* Wqkv  = (const float*)d_in[3];
    const float* bqkv  = (const float*)d_in[4];
    const float* Wout  = (const float*)d_in[5];
    const float* bout  = (const float*)d_in[6];
    float* out = (float*)d_out;

    cudaFuncSetAttribute(mma_gemm_kernel,
                         cudaFuncAttributeMaxDynamicSharedMemorySize, GEMM_SMEM);
    cudaFuncSetAttribute(attn_mma_kernel,
                         cudaFuncAttributeMaxDynamicSharedMemorySize, ATTN_SMEM);

    __nv_bfloat16 *xhi, *xlo, *w1hi, *w1lo, *w2hi, *w2lo, *aohi, *aolo;
    cudaGetSymbolAddress((void**)&xhi,  g_Xhi);
    cudaGetSymbolAddress((void**)&xlo,  g_Xlo);
    cudaGetSymbolAddress((void**)&w1hi, g_W1hi);
    cudaGetSymbolAddress((void**)&w1lo, g_W1lo);
    cudaGetSymbolAddress((void**)&w2hi, g_W2hi);
    cudaGetSymbolAddress((void**)&w2lo, g_W2lo);
    cudaGetSymbolAddress((void**)&aohi, g_AOhi);
    cudaGetSymbolAddress((void**)&aolo, g_AOlo);

    conv_split_kernel<<<(MROWS * DIM / 4 + 255) / 256, 256>>>(x, xhi, xlo,
                                                              MROWS * DIM / 4);
    conv_transpose_kernel<<<dim3(DIM / 32, QKVN / 32), dim3(32, 8)>>>(
        Wqkv, w1hi, w1lo, DIM, QKVN);
    conv_transpose_kernel<<<dim3(DIM / 32, DIM / 32), dim3(32, 8)>>>(
        Wout, w2hi, w2lo, DIM, DIM);
    mb_kernel<<<(BATCH * SEQ * SEQ / 8 + 255) / 256, 256>>>(
        mask, bias, BATCH * SEQ * SEQ / 8);

    mma_gemm_kernel<<<dim3(QKVN / 128, MROWS / 128), 256, GEMM_SMEM>>>(
        xhi, xlo, w1hi, w1lo, bqkv, nullptr, 1);

    attn_mma_kernel<<<dim3(SEQ / 128, BATCH * NH), 256, ATTN_SMEM>>>();

    mma_gemm_kernel<<<dim3(DIM / 128, MROWS / 128), 256, GEMM_SMEM>>>(
        aohi, aolo, w2hi, w2lo, bout, out, 0);
}

// round 6
// speedup vs baseline: 3.5600x; 1.3032x over previous
#include <cuda_runtime.h>
#include <cuda_bf16.h>
#include <cuda_fp16.h>

#define BATCH 2
#define SEQ   2048
#define DIM   1024
#define NH    16
#define HD    64
#define MROWS (BATCH*SEQ)   // 4096
#define QKVN  (3*DIM)       // 3072
#define LOG2E 1.4426950408889634f

// ---------------- scratch (__device__ globals; no runtime allocs) ----------
__device__ __half g_Qh[(size_t)BATCH*NH*SEQ*HD];     // fp16, pre-scaled 0.125
__device__ __half g_Kh[(size_t)BATCH*NH*SEQ*HD];
__device__ __half g_Vh[(size_t)BATCH*NH*SEQ*HD];
__device__ __nv_bfloat16 g_Xhi[(size_t)MROWS*DIM];
__device__ __nv_bfloat16 g_Xlo[(size_t)MROWS*DIM];
__device__ __nv_bfloat16 g_W1hi[(size_t)QKVN*DIM];   // Wqkv^T [3072][1024]
__device__ __nv_bfloat16 g_W1lo[(size_t)QKVN*DIM];
__device__ __nv_bfloat16 g_W2hi[(size_t)DIM*DIM];    // Wout^T [1024][1024]
__device__ __nv_bfloat16 g_W2lo[(size_t)DIM*DIM];
__device__ __nv_bfloat16 g_AOhi[(size_t)MROWS*DIM];  // attention out hi/lo
__device__ __nv_bfloat16 g_AOlo[(size_t)MROWS*DIM];
__device__ __half g_MB[(size_t)BATCH*SEQ*SEQ];       // mask + bias (fp16)

// ---------------- helpers ---------------------------------------------------
__device__ __forceinline__ unsigned smem_u32(const void* p) {
    unsigned a;
    asm("{ .reg .u64 t; cvta.to.shared.u64 t, %1; cvt.u32.u64 %0, t; }"
        : "=r"(a) : "l"(p));
    return a;
}
__device__ __forceinline__ void ldsm4(unsigned& r0, unsigned& r1,
                                      unsigned& r2, unsigned& r3, unsigned a) {
    asm volatile("ldmatrix.sync.aligned.m8n8.x4.shared.b16 {%0,%1,%2,%3}, [%4];"
                 : "=r"(r0), "=r"(r1), "=r"(r2), "=r"(r3) : "r"(a));
}
__device__ __forceinline__ void ldsm4t(unsigned& r0, unsigned& r1,
                                       unsigned& r2, unsigned& r3, unsigned a) {
    asm volatile("ldmatrix.sync.aligned.m8n8.x4.trans.shared.b16 {%0,%1,%2,%3}, [%4];"
                 : "=r"(r0), "=r"(r1), "=r"(r2), "=r"(r3) : "r"(a));
}
__device__ __forceinline__ void mma_bf16(float* c, const unsigned* a,
                                         unsigned b0, unsigned b1) {
    asm volatile(
        "mma.sync.aligned.m16n8k16.row.col.f32.bf16.bf16.f32 "
        "{%0,%1,%2,%3}, {%4,%5,%6,%7}, {%8,%9}, {%0,%1,%2,%3};"
        : "+f"(c[0]), "+f"(c[1]), "+f"(c[2]), "+f"(c[3])
        : "r"(a[0]), "r"(a[1]), "r"(a[2]), "r"(a[3]), "r"(b0), "r"(b1));
}
__device__ __forceinline__ void mma_f16(float* c, const unsigned* a,
                                        unsigned b0, unsigned b1) {
    asm volatile(
        "mma.sync.aligned.m16n8k16.row.col.f32.f16.f16.f32 "
        "{%0,%1,%2,%3}, {%4,%5,%6,%7}, {%8,%9}, {%0,%1,%2,%3};"
        : "+f"(c[0]), "+f"(c[1]), "+f"(c[2]), "+f"(c[3])
        : "r"(a[0]), "r"(a[1]), "r"(a[2]), "r"(a[3]), "r"(b0), "r"(b1));
}
__device__ __forceinline__ void cp16(unsigned dst, const void* src) {
    asm volatile("cp.async.cg.shared.global [%0], [%1], 16;"
                 :: "r"(dst), "l"(src) : "memory");
}
__device__ __forceinline__ void cp_commit() {
    asm volatile("cp.async.commit_group;" ::: "memory");
}
__device__ __forceinline__ void split2(float a, float b, unsigned& hi, unsigned& lo) {
    float ha = __bfloat162float(__float2bfloat16(a));
    float hb = __bfloat162float(__float2bfloat16(b));
    asm("cvt.rn.bf16x2.f32 %0, %1, %2;" : "=r"(hi) : "f"(hb), "f"(ha));
    asm("cvt.rn.bf16x2.f32 %0, %1, %2;" : "=r"(lo) : "f"(b - hb), "f"(a - ha));
}
__device__ __forceinline__ unsigned packh2(float a, float b) {
    unsigned r;
    asm("cvt.rn.f16x2.f32 %0, %1, %2;" : "=r"(r) : "f"(b), "f"(a));
    return r;
}
// fast 2^t on the FMA pipe (t <= 0, clamped; ~2e-6 rel err)
__device__ __forceinline__ float fexp2(float t) {
    t = fmaxf(t, -100.f);
    float fi = rintf(t);
    float f = t - fi;
    float p = 1.3333558e-3f;
    p = fmaf(p, f, 9.6181291e-3f);
    p = fmaf(p, f, 5.5504109e-2f);
    p = fmaf(p, f, 2.4022651e-1f);
    p = fmaf(p, f, 6.9314718e-1f);
    p = fmaf(p, f, 1.0f);
    return __int_as_float(__float_as_int(p) + (((int)fi) << 23));
}
// swizzled offset in a [rows][32 bf16] tile (64B rows)
__device__ __forceinline__ unsigned swz64(int row, unsigned colb) {
    return (unsigned)(row * 64) + (colb ^ (((unsigned)(row >> 1) & 3u) << 4));
}

#define GEMM_SMEM (3*32768)     // 3 stages x (Ahi|Alo|Bhi|Blo) 8KB tiles

// ---------------------------------------------------------------------------
// conversions
// ---------------------------------------------------------------------------
__global__ __launch_bounds__(256) void conv_split_kernel(
    const float* __restrict__ src, __nv_bfloat16* __restrict__ hi,
    __nv_bfloat16* __restrict__ lo, int n4)
{
    int i = blockIdx.x * 256 + threadIdx.x;
    if (i >= n4) return;
    float4 v = *((const float4*)src + i);
    unsigned h01, h23, l01, l23;
    split2(v.x, v.y, h01, l01);
    split2(v.z, v.w, h23, l23);
    ((unsigned*)hi)[i*2+0] = h01;
    ((unsigned*)hi)[i*2+1] = h23;
    ((unsigned*)lo)[i*2+0] = l01;
    ((unsigned*)lo)[i*2+1] = l23;
}

__global__ void conv_transpose_kernel(
    const float* __restrict__ W, __nv_bfloat16* __restrict__ Thi,
    __nv_bfloat16* __restrict__ Tlo, int K, int N)
{
    __shared__ float t[32][33];
    const int k0 = blockIdx.x * 32, n0 = blockIdx.y * 32;
    const int tx = threadIdx.x, ty = threadIdx.y;
    for (int i = ty; i < 32; i += 8)
        t[i][tx] = W[(size_t)(k0 + i) * N + n0 + tx];
    __syncthreads();
    for (int i = ty; i < 32; i += 8) {
        float v = t[tx][i];
        __nv_bfloat16 h = __float2bfloat16(v);
        Thi[(size_t)(n0 + i) * K + k0 + tx] = h;
        Tlo[(size_t)(n0 + i) * K + k0 + tx] =
            __float2bfloat16(v - __bfloat162float(h));
    }
}

// combined mask+bias in fp16
__global__ __launch_bounds__(256) void mb_kernel(
    const float* __restrict__ mask, const float* __restrict__ bias, int n8)
{
    int i = blockIdx.x * 256 + threadIdx.x;
    if (i >= n8) return;
    const int per_b = SEQ * SEQ / 8;
    int r = i % per_b;
    float4 m0 = ((const float4*)mask)[r*2+0];
    float4 m1 = ((const float4*)mask)[r*2+1];
    float4 b0 = ((const float4*)bias)[i*2+0];
    float4 b1 = ((const float4*)bias)[i*2+1];
    __half2 o[4];
    o[0] = __floats2half2_rn(m0.x + b0.x, m0.y + b0.y);
    o[1] = __floats2half2_rn(m0.z + b0.z, m0.w + b0.w);
    o[2] = __floats2half2_rn(m1.x + b1.x, m1.y + b1.y);
    o[3] = __floats2half2_rn(m1.z + b1.z, m1.w + b1.w);
    ((uint4*)g_MB)[i] = *(uint4*)o;
}

// ---------------------------------------------------------------------------
// HMMA split-bf16 GEMM. BK=32, 3-stage cp.async pipeline, 2 CTAs/SM.
// mode 0: out fp32 + bias. mode 1: emit fp16 Q (scaled 0.125) / K / V.
// ---------------------------------------------------------------------------
__global__ __launch_bounds__(256, 2) void mma_gemm_kernel(
    const __nv_bfloat16* __restrict__ Ahi, const __nv_bfloat16* __restrict__ Alo,
    const __nv_bfloat16* __restrict__ Bhi, const __nv_bfloat16* __restrict__ Blo,
    const float* __restrict__ bias, float* __restrict__ out, int mode)
{
    extern __shared__ char smraw[];
    const unsigned sbase = smem_u32(smraw);
    const int tid  = threadIdx.x;
    const int wid  = tid >> 5;
    const int lane = tid & 31;
    const int warp_m = wid & 3;
    const int warp_n = wid >> 2;
    const int row_a = blockIdx.y * 128;
    const int col0  = blockIdx.x * 128;

    float acc[2][8][4];
#pragma unroll
    for (int i = 0; i < 2; i++)
#pragma unroll
        for (int j = 0; j < 8; j++)
#pragma unroll
            for (int c = 0; c < 4; c++) acc[i][j][c] = 0.f;

    auto issue = [&](int t) {
        const int k0 = t * 32;
        const unsigned stage = (unsigned)((t % 3) * 32768);
#pragma unroll
        for (int p = 0; p < 4; p++) {
            const __nv_bfloat16* src = (p == 0) ? Ahi : (p == 1) ? Alo
                                     : (p == 2) ? Bhi : Blo;
            const int rb = (p < 2) ? row_a : col0;
            const unsigned pb = stage + (unsigned)p * 8192u;
#pragma unroll
            for (int i = 0; i < 2; i++) {
                const int e = tid + i * 256;
                const int r = e >> 2, c16 = e & 3;
                cp16(sbase + pb + swz64(r, (unsigned)(c16 * 16)),
                     src + (size_t)(rb + r) * DIM + k0 + c16 * 8);
            }
        }
        cp_commit();
    };

    issue(0); issue(1); issue(2);

    const int amat = lane >> 3;
    const int arow_l = (lane & 7) + ((amat & 1) << 3);
    const unsigned acolx = (unsigned)((amat >> 1) << 4);
    const int brow_l = (lane & 7) + ((amat >> 1) << 3);
    const unsigned bcolx = (unsigned)((amat & 1) << 4);

    for (int t = 0; t < 32; t++) {
        if (t <= 29)      asm volatile("cp.async.wait_group 2;" ::: "memory");
        else if (t == 30) asm volatile("cp.async.wait_group 1;" ::: "memory");
        else              asm volatile("cp.async.wait_group 0;" ::: "memory");
        __syncthreads();

        const unsigned stage = sbase + (unsigned)((t % 3) * 32768);
#pragma unroll
        for (int ks = 0; ks < 2; ks++) {
            const unsigned kb = (unsigned)(ks * 32);
            unsigned bh[4][4], bl[4][4];
#pragma unroll
            for (int np = 0; np < 4; np++) {
                const int r = warp_n * 64 + np * 16 + brow_l;
                const unsigned ro = swz64(r, kb + bcolx);
                ldsm4(bh[np][0], bh[np][1], bh[np][2], bh[np][3], stage + 16384 + ro);
                ldsm4(bl[np][0], bl[np][1], bl[np][2], bl[np][3], stage + 24576 + ro);
            }
#pragma unroll
            for (int mf = 0; mf < 2; mf++) {
                const int r = warp_m * 32 + mf * 16 + arow_l;
                const unsigned ro = swz64(r, kb + acolx);
                unsigned ah[4], al[4];
                ldsm4(ah[0], ah[1], ah[2], ah[3], stage + ro);
                ldsm4(al[0], al[1], al[2], al[3], stage + 8192 + ro);
#pragma unroll
                for (int nn = 0; nn < 8; nn++) {
                    const int np = nn >> 1, hf = (nn & 1) * 2;
                    mma_bf16(acc[mf][nn], ah, bh[np][hf], bh[np][hf + 1]);
                    mma_bf16(acc[mf][nn], ah, bl[np][hf], bl[np][hf + 1]);
                    mma_bf16(acc[mf][nn], al, bh[np][hf], bh[np][hf + 1]);
                }
            }
        }
        __syncthreads();
        if (t + 3 < 32) issue(t + 3);
    }

#pragma unroll
    for (int mf = 0; mf < 2; mf++) {
#pragma unroll
        for (int nn = 0; nn < 8; nn++) {
            const int gc = col0 + warp_n * 64 + nn * 8 + (lane & 3) * 2;
            const int r0 = row_a + warp_m * 32 + mf * 16 + (lane >> 2);
            const float bx = bias[gc], by = bias[gc + 1];
            float2 v0, v1;
            v0.x = acc[mf][nn][0] + bx; v0.y = acc[mf][nn][1] + by;
            v1.x = acc[mf][nn][2] + bx; v1.y = acc[mf][nn][3] + by;
            if (mode == 0) {
                *(float2*)(out + (size_t)r0 * DIM + gc)       = v0;
                *(float2*)(out + (size_t)(r0 + 8) * DIM + gc) = v1;
            } else {
                const int sel = gc >> 10;
                const int w   = gc & 1023;
                const int h   = w >> 6;
                const int d0  = w & 63;
                __half* dst;
                float sc;
                if (sel == 0)      { dst = g_Qh; sc = 0.125f; }
                else if (sel == 1) { dst = g_Kh; sc = 1.f; }
                else               { dst = g_Vh; sc = 1.f; }
                const int b0 = r0 >> 11, s0 = r0 & 2047;
                const int r1 = r0 + 8;
                const int b1 = r1 >> 11, s1 = r1 & 2047;
                const size_t i0 = (((size_t)b0 * NH + h) * SEQ + s0) * HD + d0;
                const size_t i1 = (((size_t)b1 * NH + h) * SEQ + s1) * HD + d0;
                *(unsigned*)(dst + i0) = packh2(v0.x * sc, v0.y * sc);
                *(unsigned*)(dst + i1) = packh2(v1.x * sc, v1.y * sc);
            }
        }
    }
}

// ---------------------------------------------------------------------------
// fp16 tensor-core flash attention. 128 q x 64 k tiles, 8 warps, 2 CTAs/SM.
// Q[16KB] + 2 stages of (K 8KB | V 8KB).
// ---------------------------------------------------------------------------
#define ATTN_SMEM (16384 + 2*16384)

__global__ __launch_bounds__(256, 2) void attn_mma_kernel()
{
    extern __shared__ char smraw[];
    const unsigned sbase = smem_u32(smraw);
    const int tid = threadIdx.x, wid = tid >> 5, lane = tid & 31;
    const int bh = blockIdx.y, b = bh >> 4, h = bh & 15;
    const int q0 = blockIdx.x * 128;

    const __half* Qg = g_Qh + (size_t)bh * SEQ * HD;
    const __half* Kg = g_Kh + (size_t)bh * SEQ * HD;
    const __half* Vg = g_Vh + (size_t)bh * SEQ * HD;

    // Q tile -> smem (128B rows, 128B swizzle)
#pragma unroll
    for (int i = 0; i < 4; i++) {
        const int e = tid + i * 256;           // 0..1023
        const int r = e >> 3, c4 = e & 7;
        unsigned off = (unsigned)(r * 128 + c4 * 16);
        off ^= (off >> 3) & 0x70;
        cp16(sbase + off, Qg + (size_t)(q0 + r) * HD + c4 * 8);
    }
    cp_commit();

    auto issue = [&](int t) {
        const int k0 = t * 64;
        const unsigned stg = 16384u + (unsigned)((t & 1) * 16384);
#pragma unroll
        for (int p = 0; p < 2; p++) {
            const __half* src = p ? Vg : Kg;
#pragma unroll
            for (int i = 0; i < 2; i++) {
                const int e = tid + i * 256;   // 0..511
                const int r = e >> 3, c4 = e & 7;
                unsigned off = (unsigned)(r * 128 + c4 * 16);
                off ^= (off >> 3) & 0x70;
                cp16(sbase + stg + (unsigned)p * 8192u + off,
                     src + (size_t)(k0 + r) * HD + c4 * 8);
            }
        }
        cp_commit();
    };
    issue(0);

    const int amat = lane >> 3;
    const int arow = wid * 16 + (lane & 7) + ((amat & 1) << 3);
    const unsigned acolx = (unsigned)((amat >> 1) << 4);
    const int krow_b = (lane & 7) + ((amat >> 1) << 3);
    const unsigned kcolx = (unsigned)((amat & 1) << 4);
    const int vrow_b = (lane & 7) + ((amat & 1) << 3);
    const unsigned vcolb = (unsigned)((lane >> 4) << 4);

    const __half* mbp = g_MB + ((size_t)b * SEQ + q0 + wid * 16 + (lane >> 2)) * SEQ
                        + (lane & 3) * 2;

    float o[8][4];
#pragma unroll
    for (int nn = 0; nn < 8; nn++)
#pragma unroll
        for (int c = 0; c < 4; c++) o[nn][c] = 0.f;
    float sM0 = -1e30f, sM1 = -1e30f, sL0 = 0.f, sL1 = 0.f;

    for (int t = 0; t < 32; t++) {
        if (t + 1 < 32) {
            issue(t + 1);
            asm volatile("cp.async.wait_group 1;" ::: "memory");
        } else {
            asm volatile("cp.async.wait_group 0;" ::: "memory");
        }
        __syncthreads();
        const unsigned stg = sbase + 16384u + (unsigned)((t & 1) * 16384);

        // ---- S = Q.K^T (fp16) ----
        float s[8][4];
#pragma unroll
        for (int nn = 0; nn < 8; nn++)
#pragma unroll
            for (int c = 0; c < 4; c++) s[nn][c] = 0.f;
#pragma unroll
        for (int ks = 0; ks < 4; ks++) {
            unsigned qoff = (unsigned)(arow * 128)
                          + (((unsigned)(ks * 32) + acolx) ^ (((unsigned)(arow & 7)) << 4));
            unsigned qf[4];
            ldsm4(qf[0], qf[1], qf[2], qf[3], sbase + qoff);
#pragma unroll
            for (int np = 0; np < 4; np++) {
                const int kr = np * 16 + krow_b;
                unsigned off = (unsigned)(kr * 128)
                             + (((unsigned)(ks * 32) + kcolx) ^ (((unsigned)(kr & 7)) << 4));
                unsigned kf[4];
                ldsm4(kf[0], kf[1], kf[2], kf[3], stg + off);
                mma_f16(s[2*np],   qf, kf[0], kf[1]);
                mma_f16(s[2*np+1], qf, kf[2], kf[3]);
            }
        }

        // ---- + mask + bias (fp16) ----
        const __half* mrow = mbp + t * 64;
#pragma unroll
        for (int nn = 0; nn < 8; nn++) {
            float2 f0 = __half22float2(*(const __half2*)(mrow + nn * 8));
            float2 f1 = __half22float2(*(const __half2*)(mrow + 8 * SEQ + nn * 8));
            s[nn][0] += f0.x; s[nn][1] += f0.y;
            s[nn][2] += f1.x; s[nn][3] += f1.y;
        }

        // ---- online softmax (2 rows/thread) ----
        float mx0 = -1e30f, mx1 = -1e30f;
#pragma unroll
        for (int nn = 0; nn < 8; nn++) {
            mx0 = fmaxf(mx0, fmaxf(s[nn][0], s[nn][1]));
            mx1 = fmaxf(mx1, fmaxf(s[nn][2], s[nn][3]));
        }
        mx0 = fmaxf(mx0, __shfl_xor_sync(0xffffffffu, mx0, 1));
        mx0 = fmaxf(mx0, __shfl_xor_sync(0xffffffffu, mx0, 2));
        mx1 = fmaxf(mx1, __shfl_xor_sync(0xffffffffu, mx1, 1));
        mx1 = fmaxf(mx1, __shfl_xor_sync(0xffffffffu, mx1, 2));
        const float mn0 = fmaxf(sM0, mx0), mn1 = fmaxf(sM1, mx1);
        const float c0 = fexp2((sM0 - mn0) * LOG2E);
        const float c1 = fexp2((sM1 - mn1) * LOG2E);
        sM0 = mn0; sM1 = mn1;
        float sum0 = 0.f, sum1 = 0.f;
#pragma unroll
        for (int nn = 0; nn < 8; nn++) {
            s[nn][0] = fexp2((s[nn][0] - mn0) * LOG2E); sum0 += s[nn][0];
            s[nn][1] = fexp2((s[nn][1] - mn0) * LOG2E); sum0 += s[nn][1];
            s[nn][2] = fexp2((s[nn][2] - mn1) * LOG2E); sum1 += s[nn][2];
            s[nn][3] = fexp2((s[nn][3] - mn1) * LOG2E); sum1 += s[nn][3];
        }
        sum0 += __shfl_xor_sync(0xffffffffu, sum0, 1);
        sum0 += __shfl_xor_sync(0xffffffffu, sum0, 2);
        sum1 += __shfl_xor_sync(0xffffffffu, sum1, 1);
        sum1 += __shfl_xor_sync(0xffffffffu, sum1, 2);
        sL0 = sL0 * c0 + sum0;
        sL1 = sL1 * c1 + sum1;
#pragma unroll
        for (int nn = 0; nn < 8; nn++) {
            o[nn][0] *= c0; o[nn][1] *= c0;
            o[nn][2] *= c1; o[nn][3] *= c1;
        }

        // ---- O += P.V (fp16) ----
#pragma unroll
        for (int ks = 0; ks < 4; ks++) {
            unsigned pa[4];
            pa[0] = packh2(s[2*ks][0],   s[2*ks][1]);
            pa[1] = packh2(s[2*ks][2],   s[2*ks][3]);
            pa[2] = packh2(s[2*ks+1][0], s[2*ks+1][1]);
            pa[3] = packh2(s[2*ks+1][2], s[2*ks+1][3]);
#pragma unroll
            for (int np = 0; np < 4; np++) {
                const int vr = ks * 16 + vrow_b;
                unsigned off = (unsigned)(vr * 128)
                             + (((unsigned)(np * 32) + vcolb) ^ (((unsigned)(vr & 7)) << 4));
                unsigned vf[4];
                ldsm4t(vf[0], vf[1], vf[2], vf[3], stg + 8192 + off);
                mma_f16(o[2*np],   pa, vf[0], vf[1]);
                mma_f16(o[2*np+1], pa, vf[2], vf[3]);
            }
        }
        __syncthreads();
    }

    // ---- normalize + emit bf16 hi/lo into g_AO ----
    const float inv0 = 1.f / sL0, inv1 = 1.f / sL1;
    const int qr = q0 + wid * 16 + (lane >> 2);
    const size_t base0 = ((size_t)(b * SEQ + qr)) * DIM + h * HD;
    const size_t base1 = base0 + (size_t)8 * DIM;
#pragma unroll
    for (int nn = 0; nn < 8; nn++) {
        const int c = nn * 8 + (lane & 3) * 2;
        unsigned hv, lv;
        split2(o[nn][0] * inv0, o[nn][1] * inv0, hv, lv);
        *(unsigned*)(g_AOhi + base0 + c) = hv;
        *(unsigned*)(g_AOlo + base0 + c) = lv;
        split2(o[nn][2] * inv1, o[nn][3] * inv1, hv, lv);
        *(unsigned*)(g_AOhi + base1 + c) = hv;
        *(unsigned*)(g_AOlo + base1 + c) = lv;
    }
}

// ---------------------------------------------------------------------------
extern "C" void kernel_launch(void* const* d_in, const int* in_sizes, int n_in,
                              void* d_out, int out_size)
{
    const float* x     = (const float*)d_in[0];
    const float* mask  = (const float*)d_in[1];
    const float* bias  = (const float*)d_in[2];
    const float* Wqkv  = (const float*)d_in[3];
    const float* bqkv  = (const float*)d_in[4];
    const float* Wout  = (const float*)d_in[5];
    const float* bout  = (const float*)d_in[6];
    float* out = (float*)d_out;

    cudaFuncSetAttribute(mma_gemm_kernel,
                         cudaFuncAttributeMaxDynamicSharedMemorySize, GEMM_SMEM);
    cudaFuncSetAttribute(attn_mma_kernel,
                         cudaFuncAttributeMaxDynamicSharedMemorySize, ATTN_SMEM);

    __nv_bfloat16 *xhi, *xlo, *w1hi, *w1lo, *w2hi, *w2lo, *aohi, *aolo;
    cudaGetSymbolAddress((void**)&xhi,  g_Xhi);
    cudaGetSymbolAddress((void**)&xlo,  g_Xlo);
    cudaGetSymbolAddress((void**)&w1hi, g_W1hi);
    cudaGetSymbolAddress((void**)&w1lo, g_W1lo);
    cudaGetSymbolAddress((void**)&w2hi, g_W2hi);
    cudaGetSymbolAddress((void**)&w2lo, g_W2lo);
    cudaGetSymbolAddress((void**)&aohi, g_AOhi);
    cudaGetSymbolAddress((void**)&aolo, g_AOlo);

    conv_split_kernel<<<(MROWS * DIM / 4 + 255) / 256, 256>>>(x, xhi, xlo,
                                                              MROWS * DIM / 4);
    conv_transpose_kernel<<<dim3(DIM / 32, QKVN / 32), dim3(32, 8)>>>(
        Wqkv, w1hi, w1lo, DIM, QKVN);
    conv_transpose_kernel<<<dim3(DIM / 32, DIM / 32), dim3(32, 8)>>>(
        Wout, w2hi, w2lo, DIM, DIM);
    mb_kernel<<<(BATCH * SEQ * SEQ / 8 + 255) / 256, 256>>>(
        mask, bias, BATCH * SEQ * SEQ / 8);

    mma_gemm_kernel<<<dim3(QKVN / 128, MROWS / 128), 256, GEMM_SMEM>>>(
        xhi, xlo, w1hi, w1lo, bqkv, nullptr, 1);

    attn_mma_kernel<<<dim3(SEQ / 128, BATCH * NH), 256, ATTN_SMEM>>>();

    mma_gemm_kernel<<<dim3(DIM / 128, MROWS / 128), 256, GEMM_SMEM>>>(
        aohi, aolo, w2hi, w2lo, bout, out, 0);
}

// round 7
// speedup vs baseline: 4.3568x; 1.2238x over previous
#include <cuda_runtime.h>
#include <cuda_bf16.h>
#include <cuda_fp16.h>

#define BATCH 2
#define SEQ   2048
#define DIM   1024
#define NH    16
#define HD    64
#define MROWS (BATCH*SEQ)   // 4096
#define QKVN  (3*DIM)       // 3072
#define LOG2E 1.4426950408889634f

// ---------------- scratch (__device__ globals; no runtime allocs) ----------
__device__ __half g_Qh[(size_t)BATCH*NH*SEQ*HD];     // fp16, pre-scaled 0.125
__device__ __half g_Kh[(size_t)BATCH*NH*SEQ*HD];
__device__ __half g_Vh[(size_t)BATCH*NH*SEQ*HD];
__device__ __half g_X16[(size_t)MROWS*DIM];          // x in fp16
__device__ __half g_W1hi[(size_t)QKVN*DIM];          // Wqkv^T hi/lo fp16
__device__ __half g_W1lo[(size_t)QKVN*DIM];
__device__ __half g_W2hi[(size_t)DIM*DIM];           // Wout^T hi/lo fp16
__device__ __half g_W2lo[(size_t)DIM*DIM];
__device__ __half g_AOh[(size_t)MROWS*DIM];          // attention out fp16
__device__ __half g_MB[(size_t)BATCH*SEQ*SEQ];       // mask + bias (fp16)

// ---------------- helpers ---------------------------------------------------
__device__ __forceinline__ unsigned smem_u32(const void* p) {
    unsigned a;
    asm("{ .reg .u64 t; cvta.to.shared.u64 t, %1; cvt.u32.u64 %0, t; }"
        : "=r"(a) : "l"(p));
    return a;
}
__device__ __forceinline__ void ldsm4(unsigned& r0, unsigned& r1,
                                      unsigned& r2, unsigned& r3, unsigned a) {
    asm volatile("ldmatrix.sync.aligned.m8n8.x4.shared.b16 {%0,%1,%2,%3}, [%4];"
                 : "=r"(r0), "=r"(r1), "=r"(r2), "=r"(r3) : "r"(a));
}
__device__ __forceinline__ void ldsm4t(unsigned& r0, unsigned& r1,
                                       unsigned& r2, unsigned& r3, unsigned a) {
    asm volatile("ldmatrix.sync.aligned.m8n8.x4.trans.shared.b16 {%0,%1,%2,%3}, [%4];"
                 : "=r"(r0), "=r"(r1), "=r"(r2), "=r"(r3) : "r"(a));
}
__device__ __forceinline__ void mma_f16(float* c, const unsigned* a,
                                        unsigned b0, unsigned b1) {
    asm volatile(
        "mma.sync.aligned.m16n8k16.row.col.f32.f16.f16.f32 "
        "{%0,%1,%2,%3}, {%4,%5,%6,%7}, {%8,%9}, {%0,%1,%2,%3};"
        : "+f"(c[0]), "+f"(c[1]), "+f"(c[2]), "+f"(c[3])
        : "r"(a[0]), "r"(a[1]), "r"(a[2]), "r"(a[3]), "r"(b0), "r"(b1));
}
__device__ __forceinline__ void cp16(unsigned dst, const void* src) {
    asm volatile("cp.async.cg.shared.global [%0], [%1], 16;"
                 :: "r"(dst), "l"(src) : "memory");
}
__device__ __forceinline__ void cp_commit() {
    asm volatile("cp.async.commit_group;" ::: "memory");
}
__device__ __forceinline__ unsigned packh2(float a, float b) {
    unsigned r;
    asm("cvt.rn.f16x2.f32 %0, %1, %2;" : "=r"(r) : "f"(b), "f"(a));
    return r;
}
// fast 2^t on the FMA pipe (t <= 0, clamped; ~2e-6 rel err)
__device__ __forceinline__ float fexp2(float t) {
    t = fmaxf(t, -100.f);
    float fi = rintf(t);
    float f = t - fi;
    float p = 1.3333558e-3f;
    p = fmaf(p, f, 9.6181291e-3f);
    p = fmaf(p, f, 5.5504109e-2f);
    p = fmaf(p, f, 2.4022651e-1f);
    p = fmaf(p, f, 6.9314718e-1f);
    p = fmaf(p, f, 1.0f);
    return __int_as_float(__float_as_int(p) + (((int)fi) << 23));
}
// swizzled offset in a [rows][32 f16] tile (64B rows)
__device__ __forceinline__ unsigned swz64(int row, unsigned colb) {
    return (unsigned)(row * 64) + (colb ^ (((unsigned)(row >> 1) & 3u) << 4));
}

#define GEMM_STAGE 24576            // A 8KB | Bhi 8KB | Blo 8KB
#define GEMM_SMEM  (3*GEMM_STAGE)   // 72 KB

// ---------------------------------------------------------------------------
// conversions
// ---------------------------------------------------------------------------
__global__ __launch_bounds__(256) void conv_x16_kernel(
    const float* __restrict__ src, __half* __restrict__ dst, int n4)
{
    int i = blockIdx.x * 256 + threadIdx.x;
    if (i >= n4) return;
    float4 v = *((const float4*)src + i);
    uint2 o;
    o.x = packh2(v.x, v.y);
    o.y = packh2(v.z, v.w);
    ((uint2*)dst)[i] = o;
}

// transpose + fp16 split: W[K][N] -> T{hi,lo}[N][K]
__global__ void conv_transpose_kernel(
    const float* __restrict__ W, __half* __restrict__ Thi,
    __half* __restrict__ Tlo, int K, int N)
{
    __shared__ float t[32][33];
    const int k0 = blockIdx.x * 32, n0 = blockIdx.y * 32;
    const int tx = threadIdx.x, ty = threadIdx.y;
    for (int i = ty; i < 32; i += 8)
        t[i][tx] = W[(size_t)(k0 + i) * N + n0 + tx];
    __syncthreads();
    for (int i = ty; i < 32; i += 8) {
        float v = t[tx][i];
        __half h = __float2half(v);
        Thi[(size_t)(n0 + i) * K + k0 + tx] = h;
        Tlo[(size_t)(n0 + i) * K + k0 + tx] = __float2half(v - __half2float(h));
    }
}

// combined mask+bias in fp16
__global__ __launch_bounds__(256) void mb_kernel(
    const float* __restrict__ mask, const float* __restrict__ bias, int n8)
{
    int i = blockIdx.x * 256 + threadIdx.x;
    if (i >= n8) return;
    const int per_b = SEQ * SEQ / 8;
    int r = i % per_b;
    float4 m0 = ((const float4*)mask)[r*2+0];
    float4 m1 = ((const float4*)mask)[r*2+1];
    float4 b0 = ((const float4*)bias)[i*2+0];
    float4 b1 = ((const float4*)bias)[i*2+1];
    __half2 o[4];
    o[0] = __floats2half2_rn(m0.x + b0.x, m0.y + b0.y);
    o[1] = __floats2half2_rn(m0.z + b0.z, m0.w + b0.w);
    o[2] = __floats2half2_rn(m1.x + b1.x, m1.y + b1.y);
    o[3] = __floats2half2_rn(m1.z + b1.z, m1.w + b1.w);
    ((uint4*)g_MB)[i] = *(uint4*)o;
}

// ---------------------------------------------------------------------------
// HMMA GEMM: A fp16 single, B fp16 hi+lo split (2 MMAs). BK=32, 3-stage
// single-sync cp.async pipeline, 2 CTAs/SM.
// mode 0: out fp32 + bias. mode 1: emit fp16 Q (scaled 0.125) / K / V.
// ---------------------------------------------------------------------------
__global__ __launch_bounds__(256, 2) void mma_gemm_kernel(
    const __half* __restrict__ A,
    const __half* __restrict__ Bhi, const __half* __restrict__ Blo,
    const float* __restrict__ bias, float* __restrict__ out, int mode)
{
    extern __shared__ char smraw[];
    const unsigned sbase = smem_u32(smraw);
    const int tid  = threadIdx.x;
    const int wid  = tid >> 5;
    const int lane = tid & 31;
    const int warp_m = wid & 3;
    const int warp_n = wid >> 2;
    const int row_a = blockIdx.y * 128;
    const int col0  = blockIdx.x * 128;

    float acc[2][8][4];
#pragma unroll
    for (int i = 0; i < 2; i++)
#pragma unroll
        for (int j = 0; j < 8; j++)
#pragma unroll
            for (int c = 0; c < 4; c++) acc[i][j][c] = 0.f;

    auto issue = [&](int t) {
        const int k0 = t * 32;
        const unsigned stage = (unsigned)((t % 3) * GEMM_STAGE);
#pragma unroll
        for (int p = 0; p < 3; p++) {
            const __half* src = (p == 0) ? A : (p == 1) ? Bhi : Blo;
            const int rb = (p == 0) ? row_a : col0;
            const unsigned pb = stage + (unsigned)p * 8192u;
#pragma unroll
            for (int i = 0; i < 2; i++) {
                const int e = tid + i * 256;
                const int r = e >> 2, c16 = e & 3;
                cp16(sbase + pb + swz64(r, (unsigned)(c16 * 16)),
                     src + (size_t)(rb + r) * DIM + k0 + c16 * 8);
            }
        }
        cp_commit();
    };

    issue(0); issue(1);

    const int amat = lane >> 3;
    const int arow_l = (lane & 7) + ((amat & 1) << 3);
    const unsigned acolx = (unsigned)((amat >> 1) << 4);
    const int brow_l = (lane & 7) + ((amat >> 1) << 3);
    const unsigned bcolx = (unsigned)((amat & 1) << 4);

    for (int t = 0; t < 32; t++) {
        if (t < 31) asm volatile("cp.async.wait_group 1;" ::: "memory");
        else        asm volatile("cp.async.wait_group 0;" ::: "memory");
        __syncthreads();
        if (t + 2 < 32) issue(t + 2);

        const unsigned stage = sbase + (unsigned)((t % 3) * GEMM_STAGE);
#pragma unroll
        for (int ks = 0; ks < 2; ks++) {
            const unsigned kb = (unsigned)(ks * 32);
            unsigned bh[4][4], bl[4][4];
#pragma unroll
            for (int np = 0; np < 4; np++) {
                const int r = warp_n * 64 + np * 16 + brow_l;
                const unsigned ro = swz64(r, kb + bcolx);
                ldsm4(bh[np][0], bh[np][1], bh[np][2], bh[np][3], stage + 8192 + ro);
                ldsm4(bl[np][0], bl[np][1], bl[np][2], bl[np][3], stage + 16384 + ro);
            }
#pragma unroll
            for (int mf = 0; mf < 2; mf++) {
                const int r = warp_m * 32 + mf * 16 + arow_l;
                const unsigned ro = swz64(r, kb + acolx);
                unsigned af[4];
                ldsm4(af[0], af[1], af[2], af[3], stage + ro);
#pragma unroll
                for (int nn = 0; nn < 8; nn++) {
                    const int np = nn >> 1, hf = (nn & 1) * 2;
                    mma_f16(acc[mf][nn], af, bh[np][hf], bh[np][hf + 1]);
                    mma_f16(acc[mf][nn], af, bl[np][hf], bl[np][hf + 1]);
                }
            }
        }
    }

#pragma unroll
    for (int mf = 0; mf < 2; mf++) {
#pragma unroll
        for (int nn = 0; nn < 8; nn++) {
            const int gc = col0 + warp_n * 64 + nn * 8 + (lane & 3) * 2;
            const int r0 = row_a + warp_m * 32 + mf * 16 + (lane >> 2);
            const float bx = bias[gc], by = bias[gc + 1];
            float2 v0, v1;
            v0.x = acc[mf][nn][0] + bx; v0.y = acc[mf][nn][1] + by;
            v1.x = acc[mf][nn][2] + bx; v1.y = acc[mf][nn][3] + by;
            if (mode == 0) {
                *(float2*)(out + (size_t)r0 * DIM + gc)       = v0;
                *(float2*)(out + (size_t)(r0 + 8) * DIM + gc) = v1;
            } else {
                const int sel = gc >> 10;
                const int w   = gc & 1023;
                const int h   = w >> 6;
                const int d0  = w & 63;
                __half* dst;
                float sc;
                if (sel == 0)      { dst = g_Qh; sc = 0.125f; }
                else if (sel == 1) { dst = g_Kh; sc = 1.f; }
                else               { dst = g_Vh; sc = 1.f; }
                const int b0 = r0 >> 11, s0 = r0 & 2047;
                const int r1 = r0 + 8;
                const int b1 = r1 >> 11, s1 = r1 & 2047;
                const size_t i0 = (((size_t)b0 * NH + h) * SEQ + s0) * HD + d0;
                const size_t i1 = (((size_t)b1 * NH + h) * SEQ + s1) * HD + d0;
                *(unsigned*)(dst + i0) = packh2(v0.x * sc, v0.y * sc);
                *(unsigned*)(dst + i1) = packh2(v1.x * sc, v1.y * sc);
            }
        }
    }
}

// ---------------------------------------------------------------------------
// fp16 flash attention. 128 q x 64 k tiles, 8 warps, 2 CTAs/SM.
// Q[16KB] + 3 stages of (K 8KB | V 8KB) = 64 KB; single sync per iter.
// ---------------------------------------------------------------------------
#define ATTN_STAGE 16384
#define ATTN_SMEM  (16384 + 3*ATTN_STAGE)   // 64 KB

__global__ __launch_bounds__(256, 2) void attn_mma_kernel()
{
    extern __shared__ char smraw[];
    const unsigned sbase = smem_u32(smraw);
    const int tid = threadIdx.x, wid = tid >> 5, lane = tid & 31;
    const int bh = blockIdx.y, b = bh >> 4, h = bh & 15;
    const int q0 = blockIdx.x * 128;

    const __half* Qg = g_Qh + (size_t)bh * SEQ * HD;
    const __half* Kg = g_Kh + (size_t)bh * SEQ * HD;
    const __half* Vg = g_Vh + (size_t)bh * SEQ * HD;

    // Q tile -> smem (128B rows, 128B swizzle), own commit group
#pragma unroll
    for (int i = 0; i < 4; i++) {
        const int e = tid + i * 256;
        const int r = e >> 3, c4 = e & 7;
        unsigned off = (unsigned)(r * 128 + c4 * 16);
        off ^= (off >> 3) & 0x70;
        cp16(sbase + off, Qg + (size_t)(q0 + r) * HD + c4 * 8);
    }
    cp_commit();

    auto issue = [&](int t) {
        const int k0 = t * 64;
        const unsigned stg = 16384u + (unsigned)((t % 3) * ATTN_STAGE);
#pragma unroll
        for (int p = 0; p < 2; p++) {
            const __half* src = p ? Vg : Kg;
#pragma unroll
            for (int i = 0; i < 2; i++) {
                const int e = tid + i * 256;
                const int r = e >> 3, c4 = e & 7;
                unsigned off = (unsigned)(r * 128 + c4 * 16);
                off ^= (off >> 3) & 0x70;
                cp16(sbase + stg + (unsigned)p * 8192u + off,
                     src + (size_t)(k0 + r) * HD + c4 * 8);
            }
        }
        cp_commit();
    };
    issue(0); issue(1);

    const int amat = lane >> 3;
    const int arow = wid * 16 + (lane & 7) + ((amat & 1) << 3);
    const unsigned acolx = (unsigned)((amat >> 1) << 4);
    const int krow_b = (lane & 7) + ((amat >> 1) << 3);
    const unsigned kcolx = (unsigned)((amat & 1) << 4);
    const int vrow_b = (lane & 7) + ((amat & 1) << 3);
    const unsigned vcolb = (unsigned)((lane >> 4) << 4);

    const __half* mbp = g_MB + ((size_t)b * SEQ + q0 + wid * 16 + (lane >> 2)) * SEQ
                        + (lane & 3) * 2;

    float o[8][4];
#pragma unroll
    for (int nn = 0; nn < 8; nn++)
#pragma unroll
        for (int c = 0; c < 4; c++) o[nn][c] = 0.f;
    float sM0 = -1e30f, sM1 = -1e30f, sL0 = 0.f, sL1 = 0.f;

    for (int t = 0; t < 32; t++) {
        if (t < 31) asm volatile("cp.async.wait_group 1;" ::: "memory");
        else        asm volatile("cp.async.wait_group 0;" ::: "memory");
        __syncthreads();
        if (t + 2 < 32) issue(t + 2);

        const unsigned stg = sbase + 16384u + (unsigned)((t % 3) * ATTN_STAGE);

        // ---- S = Q.K^T (fp16) ----
        float s[8][4];
#pragma unroll
        for (int nn = 0; nn < 8; nn++)
#pragma unroll
            for (int c = 0; c < 4; c++) s[nn][c] = 0.f;
#pragma unroll
        for (int ks = 0; ks < 4; ks++) {
            unsigned qoff = (unsigned)(arow * 128)
                          + (((unsigned)(ks * 32) + acolx) ^ (((unsigned)(arow & 7)) << 4));
            unsigned qf[4];
            ldsm4(qf[0], qf[1], qf[2], qf[3], sbase + qoff);
#pragma unroll
            for (int np = 0; np < 4; np++) {
                const int kr = np * 16 + krow_b;
                unsigned off = (unsigned)(kr * 128)
                             + (((unsigned)(ks * 32) + kcolx) ^ (((unsigned)(kr & 7)) << 4));
                unsigned kf[4];
                ldsm4(kf[0], kf[1], kf[2], kf[3], stg + off);
                mma_f16(s[2*np],   qf, kf[0], kf[1]);
                mma_f16(s[2*np+1], qf, kf[2], kf[3]);
            }
        }

        // ---- + mask + bias (fp16) ----
        const __half* mrow = mbp + t * 64;
#pragma unroll
        for (int nn = 0; nn < 8; nn++) {
            float2 f0 = __half22float2(*(const __half2*)(mrow + nn * 8));
            float2 f1 = __half22float2(*(const __half2*)(mrow + 8 * SEQ + nn * 8));
            s[nn][0] += f0.x; s[nn][1] += f0.y;
            s[nn][2] += f1.x; s[nn][3] += f1.y;
        }

        // ---- online softmax (2 rows/thread) ----
        float mx0 = -1e30f, mx1 = -1e30f;
#pragma unroll
        for (int nn = 0; nn < 8; nn++) {
            mx0 = fmaxf(mx0, fmaxf(s[nn][0], s[nn][1]));
            mx1 = fmaxf(mx1, fmaxf(s[nn][2], s[nn][3]));
        }
        mx0 = fmaxf(mx0, __shfl_xor_sync(0xffffffffu, mx0, 1));
        mx0 = fmaxf(mx0, __shfl_xor_sync(0xffffffffu, mx0, 2));
        mx1 = fmaxf(mx1, __shfl_xor_sync(0xffffffffu, mx1, 1));
        mx1 = fmaxf(mx1, __shfl_xor_sync(0xffffffffu, mx1, 2));
        const float mn0 = fmaxf(sM0, mx0), mn1 = fmaxf(sM1, mx1);
        const float c0 = fexp2((sM0 - mn0) * LOG2E);
        const float c1 = fexp2((sM1 - mn1) * LOG2E);
        sM0 = mn0; sM1 = mn1;
        float sum0 = 0.f, sum1 = 0.f;
#pragma unroll
        for (int nn = 0; nn < 8; nn++) {
            s[nn][0] = fexp2((s[nn][0] - mn0) * LOG2E); sum0 += s[nn][0];
            s[nn][1] = fexp2((s[nn][1] - mn0) * LOG2E); sum0 += s[nn][1];
            s[nn][2] = fexp2((s[nn][2] - mn1) * LOG2E); sum1 += s[nn][2];
            s[nn][3] = fexp2((s[nn][3] - mn1) * LOG2E); sum1 += s[nn][3];
        }
        sum0 += __shfl_xor_sync(0xffffffffu, sum0, 1);
        sum0 += __shfl_xor_sync(0xffffffffu, sum0, 2);
        sum1 += __shfl_xor_sync(0xffffffffu, sum1, 1);
        sum1 += __shfl_xor_sync(0xffffffffu, sum1, 2);
        sL0 = sL0 * c0 + sum0;
        sL1 = sL1 * c1 + sum1;
#pragma unroll
        for (int nn = 0; nn < 8; nn++) {
            o[nn][0] *= c0; o[nn][1] *= c0;
            o[nn][2] *= c1; o[nn][3] *= c1;
        }

        // ---- O += P.V (fp16) ----
#pragma unroll
        for (int ks = 0; ks < 4; ks++) {
            unsigned pa[4];
            pa[0] = packh2(s[2*ks][0],   s[2*ks][1]);
            pa[1] = packh2(s[2*ks][2],   s[2*ks][3]);
            pa[2] = packh2(s[2*ks+1][0], s[2*ks+1][1]);
            pa[3] = packh2(s[2*ks+1][2], s[2*ks+1][3]);
#pragma unroll
            for (int np = 0; np < 4; np++) {
                const int vr = ks * 16 + vrow_b;
                unsigned off = (unsigned)(vr * 128)
                             + (((unsigned)(np * 32) + vcolb) ^ (((unsigned)(vr & 7)) << 4));
                unsigned vf[4];
                ldsm4t(vf[0], vf[1], vf[2], vf[3], stg + 8192 + off);
                mma_f16(o[2*np],   pa, vf[0], vf[1]);
                mma_f16(o[2*np+1], pa, vf[2], vf[3]);
            }
        }
    }

    // ---- normalize + emit fp16 into g_AOh ----
    const float inv0 = 1.f / sL0, inv1 = 1.f / sL1;
    const int qr = q0 + wid * 16 + (lane >> 2);
    const size_t base0 = ((size_t)(b * SEQ + qr)) * DIM + h * HD;
    const size_t base1 = base0 + (size_t)8 * DIM;
#pragma unroll
    for (int nn = 0; nn < 8; nn++) {
        const int c = nn * 8 + (lane & 3) * 2;
        *(unsigned*)(g_AOh + base0 + c) = packh2(o[nn][0] * inv0, o[nn][1] * inv0);
        *(unsigned*)(g_AOh + base1 + c) = packh2(o[nn][2] * inv1, o[nn][3] * inv1);
    }
}

// ---------------------------------------------------------------------------
extern "C" void kernel_launch(void* const* d_in, const int* in_sizes, int n_in,
                              void* d_out, int out_size)
{
    const float* x     = (const float*)d_in[0];
    const float* mask  = (const float*)d_in[1];
    const float* bias  = (const float*)d_in[2];
    const float* Wqkv  = (const float*)d_in[3];
    const float* bqkv  = (const float*)d_in[4];
    const float* Wout  = (const float*)d_in[5];
    const float* bout  = (const float*)d_in[6];
    float* out = (float*)d_out;

    cudaFuncSetAttribute(mma_gemm_kernel,
                         cudaFuncAttributeMaxDynamicSharedMemorySize, GEMM_SMEM);
    cudaFuncSetAttribute(attn_mma_kernel,
                         cudaFuncAttributeMaxDynamicSharedMemorySize, ATTN_SMEM);

    __half *x16, *w1hi, *w1lo, *w2hi, *w2lo, *aoh;
    cudaGetSymbolAddress((void**)&x16,  g_X16);
    cudaGetSymbolAddress((void**)&w1hi, g_W1hi);
    cudaGetSymbolAddress((void**)&w1lo, g_W1lo);
    cudaGetSymbolAddress((void**)&w2hi, g_W2hi);
    cudaGetSymbolAddress((void**)&w2lo, g_W2lo);
    cudaGetSymbolAddress((void**)&aoh,  g_AOh);

    conv_x16_kernel<<<(MROWS * DIM / 4 + 255) / 256, 256>>>(x, x16,
                                                            MROWS * DIM / 4);
    conv_transpose_kernel<<<dim3(DIM / 32, QKVN / 32), dim3(32, 8)>>>(
        Wqkv, w1hi, w1lo, DIM, QKVN);
    conv_transpose_kernel<<<dim3(DIM / 32, DIM / 32), dim3(32, 8)>>>(
        Wout, w2hi, w2lo, DIM, DIM);
    mb_kernel<<<(BATCH * SEQ * SEQ / 8 + 255) / 256, 256>>>(
        mask, bias, BATCH * SEQ * SEQ / 8);

    mma_gemm_kernel<<<dim3(QKVN / 128, MROWS / 128), 256, GEMM_SMEM>>>(
        x16, w1hi, w1lo, bqkv, nullptr, 1);

    attn_mma_kernel<<<dim3(SEQ / 128, BATCH * NH), 256, ATTN_SMEM>>>();

    mma_gemm_kernel<<<dim3(DIM / 128, MROWS / 128), 256, GEMM_SMEM>>>(
        aoh, w2hi, w2lo, bout, out, 0);
}

// round 8
// speedup vs baseline: 4.6145x; 1.0591x over previous
#include <cuda_runtime.h>
#include <cuda_bf16.h>
#include <cuda_fp16.h>

#define BATCH 2
#define SEQ   2048
#define DIM   1024
#define NH    16
#define HD    64
#define MROWS (BATCH*SEQ)   // 4096
#define QKVN  (3*DIM)       // 3072
#define LOG2E 1.4426950408889634f

// ---------------- scratch (__device__ globals; no runtime allocs) ----------
__device__ __half g_Qh[(size_t)BATCH*NH*SEQ*HD];     // fp16, pre-scaled 0.125*log2e
__device__ __half g_Kh[(size_t)BATCH*NH*SEQ*HD];
__device__ __half g_Vh[(size_t)BATCH*NH*SEQ*HD];
__device__ __half g_X16[(size_t)MROWS*DIM];          // x in fp16
__device__ __half g_W1hi[(size_t)QKVN*DIM];          // Wqkv^T hi/lo fp16
__device__ __half g_W1lo[(size_t)QKVN*DIM];
__device__ __half g_W2hi[(size_t)DIM*DIM];           // Wout^T hi/lo fp16
__device__ __half g_W2lo[(size_t)DIM*DIM];
__device__ __half g_AOh[(size_t)MROWS*DIM];          // attention out fp16
__device__ __half g_MB[(size_t)BATCH*SEQ*SEQ];       // (mask + bias)*log2e (fp16)

// ---------------- helpers ---------------------------------------------------
__device__ __forceinline__ unsigned smem_u32(const void* p) {
    unsigned a;
    asm("{ .reg .u64 t; cvta.to.shared.u64 t, %1; cvt.u32.u64 %0, t; }"
        : "=r"(a) : "l"(p));
    return a;
}
__device__ __forceinline__ void ldsm4(unsigned& r0, unsigned& r1,
                                      unsigned& r2, unsigned& r3, unsigned a) {
    asm volatile("ldmatrix.sync.aligned.m8n8.x4.shared.b16 {%0,%1,%2,%3}, [%4];"
                 : "=r"(r0), "=r"(r1), "=r"(r2), "=r"(r3) : "r"(a));
}
__device__ __forceinline__ void ldsm4t(unsigned& r0, unsigned& r1,
                                       unsigned& r2, unsigned& r3, unsigned a) {
    asm volatile("ldmatrix.sync.aligned.m8n8.x4.trans.shared.b16 {%0,%1,%2,%3}, [%4];"
                 : "=r"(r0), "=r"(r1), "=r"(r2), "=r"(r3) : "r"(a));
}
__device__ __forceinline__ void mma_f16(float* c, const unsigned* a,
                                        unsigned b0, unsigned b1) {
    asm volatile(
        "mma.sync.aligned.m16n8k16.row.col.f32.f16.f16.f32 "
        "{%0,%1,%2,%3}, {%4,%5,%6,%7}, {%8,%9}, {%0,%1,%2,%3};"
        : "+f"(c[0]), "+f"(c[1]), "+f"(c[2]), "+f"(c[3])
        : "r"(a[0]), "r"(a[1]), "r"(a[2]), "r"(a[3]), "r"(b0), "r"(b1));
}
__device__ __forceinline__ void cp16(unsigned dst, const void* src) {
    asm volatile("cp.async.cg.shared.global [%0], [%1], 16;"
                 :: "r"(dst), "l"(src) : "memory");
}
__device__ __forceinline__ void cp_commit() {
    asm volatile("cp.async.commit_group;" ::: "memory");
}
__device__ __forceinline__ unsigned packh2(float a, float b) {
    unsigned r;
    asm("cvt.rn.f16x2.f32 %0, %1, %2;" : "=r"(r) : "f"(b), "f"(a));
    return r;
}
// MUFU 2^t (t <= 0 here; ex2.approx handles large-negative -> 0)
__device__ __forceinline__ float ex2f(float t) {
    float r;
    asm("ex2.approx.f32 %0, %1;" : "=f"(r) : "f"(t));
    return r;
}
// swizzled offset in a [rows][32 f16] tile (64B rows)
__device__ __forceinline__ unsigned swz64(int row, unsigned colb) {
    return (unsigned)(row * 64) + (colb ^ (((unsigned)(row >> 1) & 3u) << 4));
}

#define GEMM_STAGE 24576            // A 8KB | Bhi 8KB | Blo 8KB
#define GEMM_SMEM  (3*GEMM_STAGE)   // 72 KB

// ---------------------------------------------------------------------------
// conversions
// ---------------------------------------------------------------------------
__global__ __launch_bounds__(256) void conv_x16_kernel(
    const float* __restrict__ src, __half* __restrict__ dst, int n4)
{
    int i = blockIdx.x * 256 + threadIdx.x;
    if (i >= n4) return;
    float4 v = *((const float4*)src + i);
    uint2 o;
    o.x = packh2(v.x, v.y);
    o.y = packh2(v.z, v.w);
    ((uint2*)dst)[i] = o;
}

// transpose + fp16 split: W[K][N] -> T{hi,lo}[N][K]
__global__ void conv_transpose_kernel(
    const float* __restrict__ W, __half* __restrict__ Thi,
    __half* __restrict__ Tlo, int K, int N)
{
    __shared__ float t[32][33];
    const int k0 = blockIdx.x * 32, n0 = blockIdx.y * 32;
    const int tx = threadIdx.x, ty = threadIdx.y;
    for (int i = ty; i < 32; i += 8)
        t[i][tx] = W[(size_t)(k0 + i) * N + n0 + tx];
    __syncthreads();
    for (int i = ty; i < 32; i += 8) {
        float v = t[tx][i];
        __half h = __float2half(v);
        Thi[(size_t)(n0 + i) * K + k0 + tx] = h;
        Tlo[(size_t)(n0 + i) * K + k0 + tx] = __float2half(v - __half2float(h));
    }
}

// combined (mask+bias)*log2e in fp16
__global__ __launch_bounds__(256) void mb_kernel(
    const float* __restrict__ mask, const float* __restrict__ bias, int n8)
{
    int i = blockIdx.x * 256 + threadIdx.x;
    if (i >= n8) return;
    const int per_b = SEQ * SEQ / 8;
    int r = i % per_b;
    float4 m0 = ((const float4*)mask)[r*2+0];
    float4 m1 = ((const float4*)mask)[r*2+1];
    float4 b0 = ((const float4*)bias)[i*2+0];
    float4 b1 = ((const float4*)bias)[i*2+1];
    __half2 o[4];
    o[0] = __floats2half2_rn((m0.x + b0.x) * LOG2E, (m0.y + b0.y) * LOG2E);
    o[1] = __floats2half2_rn((m0.z + b0.z) * LOG2E, (m0.w + b0.w) * LOG2E);
    o[2] = __floats2half2_rn((m1.x + b1.x) * LOG2E, (m1.y + b1.y) * LOG2E);
    o[3] = __floats2half2_rn((m1.z + b1.z) * LOG2E, (m1.w + b1.w) * LOG2E);
    ((uint4*)g_MB)[i] = *(uint4*)o;
}

// ---------------------------------------------------------------------------
// HMMA GEMM: A fp16 single, B fp16 hi+lo split (2 MMAs). BK=32, 3-stage
// single-sync cp.async pipeline, 2 CTAs/SM.
// mode 0: out fp32 + bias. mode 1: emit fp16 Q (scaled 0.125*log2e) / K / V.
// ---------------------------------------------------------------------------
__global__ __launch_bounds__(256, 2) void mma_gemm_kernel(
    const __half* __restrict__ A,
    const __half* __restrict__ Bhi, const __half* __restrict__ Blo,
    const float* __restrict__ bias, float* __restrict__ out, int mode)
{
    extern __shared__ char smraw[];
    const unsigned sbase = smem_u32(smraw);
    const int tid  = threadIdx.x;
    const int wid  = tid >> 5;
    const int lane = tid & 31;
    const int warp_m = wid & 3;
    const int warp_n = wid >> 2;
    const int row_a = blockIdx.y * 128;
    const int col0  = blockIdx.x * 128;

    float acc[2][8][4];
#pragma unroll
    for (int i = 0; i < 2; i++)
#pragma unroll
        for (int j = 0; j < 8; j++)
#pragma unroll
            for (int c = 0; c < 4; c++) acc[i][j][c] = 0.f;

    auto issue = [&](int t) {
        const int k0 = t * 32;
        const unsigned stage = (unsigned)((t % 3) * GEMM_STAGE);
#pragma unroll
        for (int p = 0; p < 3; p++) {
            const __half* src = (p == 0) ? A : (p == 1) ? Bhi : Blo;
            const int rb = (p == 0) ? row_a : col0;
            const unsigned pb = stage + (unsigned)p * 8192u;
#pragma unroll
            for (int i = 0; i < 2; i++) {
                const int e = tid + i * 256;
                const int r = e >> 2, c16 = e & 3;
                cp16(sbase + pb + swz64(r, (unsigned)(c16 * 16)),
                     src + (size_t)(rb + r) * DIM + k0 + c16 * 8);
            }
        }
        cp_commit();
    };

    issue(0); issue(1);

    const int amat = lane >> 3;
    const int arow_l = (lane & 7) + ((amat & 1) << 3);
    const unsigned acolx = (unsigned)((amat >> 1) << 4);
    const int brow_l = (lane & 7) + ((amat >> 1) << 3);
    const unsigned bcolx = (unsigned)((amat & 1) << 4);

    for (int t = 0; t < 32; t++) {
        if (t < 31) asm volatile("cp.async.wait_group 1;" ::: "memory");
        else        asm volatile("cp.async.wait_group 0;" ::: "memory");
        __syncthreads();
        if (t + 2 < 32) issue(t + 2);

        const unsigned stage = sbase + (unsigned)((t % 3) * GEMM_STAGE);
#pragma unroll
        for (int ks = 0; ks < 2; ks++) {
            const unsigned kb = (unsigned)(ks * 32);
            unsigned bh[4][4], bl[4][4];
#pragma unroll
            for (int np = 0; np < 4; np++) {
                const int r = warp_n * 64 + np * 16 + brow_l;
                const unsigned ro = swz64(r, kb + bcolx);
                ldsm4(bh[np][0], bh[np][1], bh[np][2], bh[np][3], stage + 8192 + ro);
                ldsm4(bl[np][0], bl[np][1], bl[np][2], bl[np][3], stage + 16384 + ro);
            }
#pragma unroll
            for (int mf = 0; mf < 2; mf++) {
                const int r = warp_m * 32 + mf * 16 + arow_l;
                const unsigned ro = swz64(r, kb + acolx);
                unsigned af[4];
                ldsm4(af[0], af[1], af[2], af[3], stage + ro);
#pragma unroll
                for (int nn = 0; nn < 8; nn++) {
                    const int np = nn >> 1, hf = (nn & 1) * 2;
                    mma_f16(acc[mf][nn], af, bh[np][hf], bh[np][hf + 1]);
                    mma_f16(acc[mf][nn], af, bl[np][hf], bl[np][hf + 1]);
                }
            }
        }
    }

#pragma unroll
    for (int mf = 0; mf < 2; mf++) {
#pragma unroll
        for (int nn = 0; nn < 8; nn++) {
            const int gc = col0 + warp_n * 64 + nn * 8 + (lane & 3) * 2;
            const int r0 = row_a + warp_m * 32 + mf * 16 + (lane >> 2);
            const float bx = bias[gc], by = bias[gc + 1];
            float2 v0, v1;
            v0.x = acc[mf][nn][0] + bx; v0.y = acc[mf][nn][1] + by;
            v1.x = acc[mf][nn][2] + bx; v1.y = acc[mf][nn][3] + by;
            if (mode == 0) {
                *(float2*)(out + (size_t)r0 * DIM + gc)       = v0;
                *(float2*)(out + (size_t)(r0 + 8) * DIM + gc) = v1;
            } else {
                const int sel = gc >> 10;
                const int w   = gc & 1023;
                const int h   = w >> 6;
                const int d0  = w & 63;
                __half* dst;
                float sc;
                if (sel == 0)      { dst = g_Qh; sc = 0.125f * LOG2E; }
                else if (sel == 1) { dst = g_Kh; sc = 1.f; }
                else               { dst = g_Vh; sc = 1.f; }
                const int b0 = r0 >> 11, s0 = r0 & 2047;
                const int r1 = r0 + 8;
                const int b1 = r1 >> 11, s1 = r1 & 2047;
                const size_t i0 = (((size_t)b0 * NH + h) * SEQ + s0) * HD + d0;
                const size_t i1 = (((size_t)b1 * NH + h) * SEQ + s1) * HD + d0;
                *(unsigned*)(dst + i0) = packh2(v0.x * sc, v0.y * sc);
                *(unsigned*)(dst + i1) = packh2(v1.x * sc, v1.y * sc);
            }
        }
    }
}

// ---------------------------------------------------------------------------
// fp16 flash attention (log2-domain scores, MUFU exp2).
// 128 q x 64 k tiles, 8 warps, 2 CTAs/SM, 3-stage single-sync pipeline.
// ---------------------------------------------------------------------------
#define ATTN_STAGE 16384
#define ATTN_SMEM  (16384 + 3*ATTN_STAGE)   // 64 KB

__global__ __launch_bounds__(256, 2) void attn_mma_kernel()
{
    extern __shared__ char smraw[];
    const unsigned sbase = smem_u32(smraw);
    const int tid = threadIdx.x, wid = tid >> 5, lane = tid & 31;
    const int bh = blockIdx.y, b = bh >> 4, h = bh & 15;
    const int q0 = blockIdx.x * 128;

    const __half* Qg = g_Qh + (size_t)bh * SEQ * HD;
    const __half* Kg = g_Kh + (size_t)bh * SEQ * HD;
    const __half* Vg = g_Vh + (size_t)bh * SEQ * HD;

    // Q tile -> smem (128B rows, 128B swizzle), own commit group
#pragma unroll
    for (int i = 0; i < 4; i++) {
        const int e = tid + i * 256;
        const int r = e >> 3, c4 = e & 7;
        unsigned off = (unsigned)(r * 128 + c4 * 16);
        off ^= (off >> 3) & 0x70;
        cp16(sbase + off, Qg + (size_t)(q0 + r) * HD + c4 * 8);
    }
    cp_commit();

    auto issue = [&](int t) {
        const int k0 = t * 64;
        const unsigned stg = 16384u + (unsigned)((t % 3) * ATTN_STAGE);
#pragma unroll
        for (int p = 0; p < 2; p++) {
            const __half* src = p ? Vg : Kg;
#pragma unroll
            for (int i = 0; i < 2; i++) {
                const int e = tid + i * 256;
                const int r = e >> 3, c4 = e & 7;
                unsigned off = (unsigned)(r * 128 + c4 * 16);
                off ^= (off >> 3) & 0x70;
                cp16(sbase + stg + (unsigned)p * 8192u + off,
                     src + (size_t)(k0 + r) * HD + c4 * 8);
            }
        }
        cp_commit();
    };
    issue(0); issue(1);

    const int amat = lane >> 3;
    const int arow = wid * 16 + (lane & 7) + ((amat & 1) << 3);
    const unsigned acolx = (unsigned)((amat >> 1) << 4);
    const int krow_b = (lane & 7) + ((amat >> 1) << 3);
    const unsigned kcolx = (unsigned)((amat & 1) << 4);
    const int vrow_b = (lane & 7) + ((amat & 1) << 3);
    const unsigned vcolb = (unsigned)((lane >> 4) << 4);

    const __half* mbp = g_MB + ((size_t)b * SEQ + q0 + wid * 16 + (lane >> 2)) * SEQ
                        + (lane & 3) * 2;

    float o[8][4];
#pragma unroll
    for (int nn = 0; nn < 8; nn++)
#pragma unroll
        for (int c = 0; c < 4; c++) o[nn][c] = 0.f;
    float sM0 = -1e30f, sM1 = -1e30f, sAcc0 = 0.f, sAcc1 = 0.f;

    for (int t = 0; t < 32; t++) {
        if (t < 31) asm volatile("cp.async.wait_group 1;" ::: "memory");
        else        asm volatile("cp.async.wait_group 0;" ::: "memory");
        __syncthreads();
        if (t + 2 < 32) issue(t + 2);

        const unsigned stg = sbase + 16384u + (unsigned)((t % 3) * ATTN_STAGE);

        // ---- S = Q.K^T (fp16, log2-domain) ----
        float s[8][4];
#pragma unroll
        for (int nn = 0; nn < 8; nn++)
#pragma unroll
            for (int c = 0; c < 4; c++) s[nn][c] = 0.f;
#pragma unroll
        for (int ks = 0; ks < 4; ks++) {
            unsigned qoff = (unsigned)(arow * 128)
                          + (((unsigned)(ks * 32) + acolx) ^ (((unsigned)(arow & 7)) << 4));
            unsigned qf[4];
            ldsm4(qf[0], qf[1], qf[2], qf[3], sbase + qoff);
#pragma unroll
            for (int np = 0; np < 4; np++) {
                const int kr = np * 16 + krow_b;
                unsigned off = (unsigned)(kr * 128)
                             + (((unsigned)(ks * 32) + kcolx) ^ (((unsigned)(kr & 7)) << 4));
                unsigned kf[4];
                ldsm4(kf[0], kf[1], kf[2], kf[3], stg + off);
                mma_f16(s[2*np],   qf, kf[0], kf[1]);
                mma_f16(s[2*np+1], qf, kf[2], kf[3]);
            }
        }

        // ---- + (mask+bias)*log2e (fp16) ----
        const __half* mrow = mbp + t * 64;
#pragma unroll
        for (int nn = 0; nn < 8; nn++) {
            float2 f0 = __half22float2(*(const __half2*)(mrow + nn * 8));
            float2 f1 = __half22float2(*(const __half2*)(mrow + 8 * SEQ + nn * 8));
            s[nn][0] += f0.x; s[nn][1] += f0.y;
            s[nn][2] += f1.x; s[nn][3] += f1.y;
        }

        // ---- online softmax (log2-domain, MUFU exp2) ----
        float mx0 = -1e30f, mx1 = -1e30f;
#pragma unroll
        for (int nn = 0; nn < 8; nn++) {
            mx0 = fmaxf(mx0, fmaxf(s[nn][0], s[nn][1]));
            mx1 = fmaxf(mx1, fmaxf(s[nn][2], s[nn][3]));
        }
        mx0 = fmaxf(mx0, __shfl_xor_sync(0xffffffffu, mx0, 1));
        mx0 = fmaxf(mx0, __shfl_xor_sync(0xffffffffu, mx0, 2));
        mx1 = fmaxf(mx1, __shfl_xor_sync(0xffffffffu, mx1, 1));
        mx1 = fmaxf(mx1, __shfl_xor_sync(0xffffffffu, mx1, 2));
        const float old0 = sM0, old1 = sM1;
        const float mn0 = fmaxf(sM0, mx0), mn1 = fmaxf(sM1, mx1);
        sM0 = mn0; sM1 = mn1;

        float ls0 = 0.f, ls1 = 0.f;
#pragma unroll
        for (int nn = 0; nn < 8; nn++) {
            s[nn][0] = ex2f(s[nn][0] - mn0); ls0 += s[nn][0];
            s[nn][1] = ex2f(s[nn][1] - mn0); ls0 += s[nn][1];
            s[nn][2] = ex2f(s[nn][2] - mn1); ls1 += s[nn][2];
            s[nn][3] = ex2f(s[nn][3] - mn1); ls1 += s[nn][3];
        }

        const bool changed = (mn0 != old0) || (mn1 != old1);
        if (__any_sync(0xffffffffu, changed)) {
            const float c0 = ex2f(old0 - mn0);
            const float c1 = ex2f(old1 - mn1);
            sAcc0 = sAcc0 * c0 + ls0;
            sAcc1 = sAcc1 * c1 + ls1;
#pragma unroll
            for (int nn = 0; nn < 8; nn++) {
                o[nn][0] *= c0; o[nn][1] *= c0;
                o[nn][2] *= c1; o[nn][3] *= c1;
            }
        } else {
            sAcc0 += ls0;
            sAcc1 += ls1;
        }

        // ---- O += P.V (fp16) ----
#pragma unroll
        for (int ks = 0; ks < 4; ks++) {
            unsigned pa[4];
            pa[0] = packh2(s[2*ks][0],   s[2*ks][1]);
            pa[1] = packh2(s[2*ks][2],   s[2*ks][3]);
            pa[2] = packh2(s[2*ks+1][0], s[2*ks+1][1]);
            pa[3] = packh2(s[2*ks+1][2], s[2*ks+1][3]);
#pragma unroll
            for (int np = 0; np < 4; np++) {
                const int vr = ks * 16 + vrow_b;
                unsigned off = (unsigned)(vr * 128)
                             + (((unsigned)(np * 32) + vcolb) ^ (((unsigned)(vr & 7)) << 4));
                unsigned vf[4];
                ldsm4t(vf[0], vf[1], vf[2], vf[3], stg + 8192 + off);
                mma_f16(o[2*np],   pa, vf[0], vf[1]);
                mma_f16(o[2*np+1], pa, vf[2], vf[3]);
            }
        }
    }

    // ---- final cross-lane sum reduction (c was uniform per 4-lane group) ----
    float sL0 = sAcc0, sL1 = sAcc1;
    sL0 += __shfl_xor_sync(0xffffffffu, sL0, 1);
    sL0 += __shfl_xor_sync(0xffffffffu, sL0, 2);
    sL1 += __shfl_xor_sync(0xffffffffu, sL1, 1);
    sL1 += __shfl_xor_sync(0xffffffffu, sL1, 2);

    // ---- normalize + emit fp16 into g_AOh ----
    const float inv0 = 1.f / sL0, inv1 = 1.f / sL1;
    const int qr = q0 + wid * 16 + (lane >> 2);
    const size_t base0 = ((size_t)(b * SEQ + qr)) * DIM + h * HD;
    const size_t base1 = base0 + (size_t)8 * DIM;
#pragma unroll
    for (int nn = 0; nn < 8; nn++) {
        const int c = nn * 8 + (lane & 3) * 2;
        *(unsigned*)(g_AOh + base0 + c) = packh2(o[nn][0] * inv0, o[nn][1] * inv0);
        *(unsigned*)(g_AOh + base1 + c) = packh2(o[nn][2] * inv1, o[nn][3] * inv1);
    }
}

// ---------------------------------------------------------------------------
extern "C" void kernel_launch(void* const* d_in, const int* in_sizes, int n_in,
                              void* d_out, int out_size)
{
    const float* x     = (const float*)d_in[0];
    const float* mask  = (const float*)d_in[1];
    const float* bias  = (const float*)d_in[2];
    const float* Wqkv  = (const float*)d_in[3];
    const float* bqkv  = (const float*)d_in[4];
    const float* Wout  = (const float*)d_in[5];
    const float* bout  = (const float*)d_in[6];
    float* out = (float*)d_out;

    cudaFuncSetAttribute(mma_gemm_kernel,
                         cudaFuncAttributeMaxDynamicSharedMemorySize, GEMM_SMEM);
    cudaFuncSetAttribute(attn_mma_kernel,
                         cudaFuncAttributeMaxDynamicSharedMemorySize, ATTN_SMEM);

    __half *x16, *w1hi, *w1lo, *w2hi, *w2lo, *aoh;
    cudaGetSymbolAddress((void**)&x16,  g_X16);
    cudaGetSymbolAddress((void**)&w1hi, g_W1hi);
    cudaGetSymbolAddress((void**)&w1lo, g_W1lo);
    cudaGetSymbolAddress((void**)&w2hi, g_W2hi);
    cudaGetSymbolAddress((void**)&w2lo, g_W2lo);
    cudaGetSymbolAddress((void**)&aoh,  g_AOh);

    conv_x16_kernel<<<(MROWS * DIM / 4 + 255) / 256, 256>>>(x, x16,
                                                            MROWS * DIM / 4);
    conv_transpose_kernel<<<dim3(DIM / 32, QKVN / 32), dim3(32, 8)>>>(
        Wqkv, w1hi, w1lo, DIM, QKVN);
    conv_transpose_kernel<<<dim3(DIM / 32, DIM / 32), dim3(32, 8)>>>(
        Wout, w2hi, w2lo, DIM, DIM);
    mb_kernel<<<(BATCH * SEQ * SEQ / 8 + 255) / 256, 256>>>(
        mask, bias, BATCH * SEQ * SEQ / 8);

    mma_gemm_kernel<<<dim3(QKVN / 128, MROWS / 128), 256, GEMM_SMEM>>>(
        x16, w1hi, w1lo, bqkv, nullptr, 1);

    attn_mma_kernel<<<dim3(SEQ / 128, BATCH * NH), 256, ATTN_SMEM>>>();

    mma_gemm_kernel<<<dim3(DIM / 128, MROWS / 128), 256, GEMM_SMEM>>>(
        aoh, w2hi, w2lo, bout, out, 0);
}